// round 4
// baseline (speedup 1.0000x reference)
#include <cuda_runtime.h>
#include <math.h>
#include <stdint.h>

// ---------------- problem constants ----------------
#define NN 50000
#define EE 600000
#define HH 128
#define GG 256
#define EPSF 1e-5f
#define SLOPE 0.2f
#define NSTRIPE 64
#define BCAP 64            // bucket capacity per node (Poisson(12) => P(>64) ~ 0)

// ---------------- scratch ----------------
__device__ __align__(16) float g_tmp[NN * HH];   // GEMM output
__device__ __align__(16) float g_acc[NN * HH];   // aggregated pre-BN activations
__device__ float g_dis[NN];
__device__ float g_als[NN], g_ald[NN];
__device__ int   g_deg[NN];
__device__ int   g_bkt[NN * BCAP];               // direct-bucket CSR
__device__ unsigned int g_ticket;
__device__ float g_pS[NSTRIPE * HH], g_pQ[NSTRIPE * HH];
__device__ __align__(16) float g_scale[HH], g_shift[HH];
__device__ __align__(16) float g_pooled[GG * HH];
__device__ float g_cnt[GG];

__device__ __forceinline__ float lrelu(float x) { return x > 0.f ? x : SLOPE * x; }

__device__ __forceinline__ float to_tf32(float x) {
    float r;
    asm("cvt.rna.tf32.f32 %0, %1;" : "=f"(r) : "f"(x));
    return r;
}

__device__ __forceinline__ void red_add_f4(float* p, float4 v) {
    asm volatile("red.global.add.v4.f32 [%0], {%1,%2,%3,%4};"
                 :: "l"(__cvta_generic_to_global(p)),
                    "f"(v.x), "f"(v.y), "f"(v.z), "f"(v.w)
                 : "memory");
}

// ---------------- zero + bucket CSR build ----------------
__global__ void k_zero() {
    int i = blockIdx.x * blockDim.x + threadIdx.x;
    if (i < NN) g_deg[i] = 0;
    if (i == 0) g_ticket = 0u;
    if (i < GG) g_cnt[i] = 0.f;
    if (i < GG * HH) g_pooled[i] = 0.f;
    if (i < NSTRIPE * HH) { g_pS[i] = 0.f; g_pQ[i] = 0.f; }
}
__global__ void k_fill(const int* __restrict__ src, const int* __restrict__ dst) {
    int e = blockIdx.x * blockDim.x + threadIdx.x;
    if (e >= EE) return;
    int d = dst[e];
    int pos = atomicAdd(&g_deg[d], 1);
    if (pos < BCAP) g_bkt[d * BCAP + pos] = src[e];
}
__global__ void k_dis() {
    int i = blockIdx.x * blockDim.x + threadIdx.x;
    if (i < NN) g_dis[i] = rsqrtf(1.0f + (float)g_deg[i]);
}

// ---------------- TF32 tensor-core GEMM, cp.async 2-stage pipeline ----------
// g_tmp[n,128] = A[n,128] @ W[128,128].
// BN: A = relu(g_acc*scale+shift) applied at fragment-read time.
// ATT: epilogue accumulates att dots into g_als/g_ald (pre-zeroed).
template<bool BN, bool ATT>
__global__ __launch_bounds__(256, 2)
void k_gemm(const float* __restrict__ Aext, const float* __restrict__ W,
            const float* __restrict__ av_s, const float* __restrict__ av_d) {
    __shared__ float As[2][128][20];     // [stage][row][k] raw fp32, k-chunk=16
    __shared__ float Bs[2][16][136];     // [stage][k][n]   raw fp32
    __shared__ float s_sc[128], s_sh[128], s_as[128], s_ad[128];
    const float* A = BN ? (const float*)g_acc : Aext;
    int t = threadIdx.x;
    if (t < 128) {
        if (BN)  { s_sc[t] = g_scale[t]; s_sh[t] = g_shift[t]; }
        if (ATT) { s_as[t] = av_s[t];    s_ad[t] = av_d[t]; }
    }
    int row0 = blockIdx.x * 128;
    int warpId = t >> 5, lane = t & 31;
    int wm = warpId >> 1, wn = warpId & 1;   // 4 x 2 warp grid
    int gp = lane >> 2, qi = lane & 3;

    // staging thread mapping
    int arow = t >> 2;            // 0..63 (two passes of 64 rows)
    int ac4  = (t & 3) * 4;       // 0,4,8,12
    int brow = t >> 5;            // 0..7  (two passes of 8 rows)
    int bc4  = (t & 31) * 4;

    float acc[2][8][4];
#pragma unroll
    for (int mt = 0; mt < 2; mt++)
#pragma unroll
        for (int nt = 0; nt < 8; nt++)
#pragma unroll
            for (int j = 0; j < 4; j++) acc[mt][nt][j] = 0.f;

    auto stage = [&](int st, int kt) {
#pragma unroll
        for (int p = 0; p < 2; p++) {
            int r = p * 64 + arow;
            int grow = row0 + r;
            uint32_t sa = (uint32_t)__cvta_generic_to_shared(&As[st][r][ac4]);
            const float* gp_ = &A[(size_t)grow * 128 + kt + ac4];
            int sz = (grow < NN) ? 16 : 0;
            asm volatile("cp.async.cg.shared.global [%0], [%1], 16, %2;"
                         :: "r"(sa), "l"(gp_), "r"(sz));
        }
#pragma unroll
        for (int p = 0; p < 2; p++) {
            int r = p * 8 + brow;
            uint32_t sa = (uint32_t)__cvta_generic_to_shared(&Bs[st][r][bc4]);
            const float* gp_ = &W[(kt + r) * 128 + bc4];
            asm volatile("cp.async.cg.shared.global [%0], [%1], 16, 16;"
                         :: "r"(sa), "l"(gp_));
        }
        asm volatile("cp.async.commit_group;");
    };

    auto compute = [&](int st, int kt) {
#pragma unroll
        for (int k8 = 0; k8 < 16; k8 += 8) {
            float sc0 = 0.f, sh0 = 0.f, sc4 = 0.f, sh4 = 0.f;
            if (BN) {
                sc0 = s_sc[kt + k8 + qi];     sh0 = s_sh[kt + k8 + qi];
                sc4 = s_sc[kt + k8 + qi + 4]; sh4 = s_sh[kt + k8 + qi + 4];
            }
            uint32_t a[2][4], b[8][2];
#pragma unroll
            for (int mt = 0; mt < 2; mt++) {
                int rb = wm * 32 + mt * 16 + gp;
                float a0 = As[st][rb][k8 + qi],     a1 = As[st][rb + 8][k8 + qi];
                float a2 = As[st][rb][k8 + qi + 4], a3 = As[st][rb + 8][k8 + qi + 4];
                if (BN) {
                    a0 = fmaxf(fmaf(a0, sc0, sh0), 0.f);
                    a1 = fmaxf(fmaf(a1, sc0, sh0), 0.f);
                    a2 = fmaxf(fmaf(a2, sc4, sh4), 0.f);
                    a3 = fmaxf(fmaf(a3, sc4, sh4), 0.f);
                }
                a[mt][0] = __float_as_uint(to_tf32(a0));
                a[mt][1] = __float_as_uint(to_tf32(a1));
                a[mt][2] = __float_as_uint(to_tf32(a2));
                a[mt][3] = __float_as_uint(to_tf32(a3));
            }
#pragma unroll
            for (int nt = 0; nt < 8; nt++) {
                int cb = wn * 64 + nt * 8 + gp;
                b[nt][0] = __float_as_uint(to_tf32(Bs[st][k8 + qi][cb]));
                b[nt][1] = __float_as_uint(to_tf32(Bs[st][k8 + qi + 4][cb]));
            }
#pragma unroll
            for (int mt = 0; mt < 2; mt++)
#pragma unroll
                for (int nt = 0; nt < 8; nt++) {
                    asm volatile(
                        "mma.sync.aligned.m16n8k8.row.col.f32.tf32.tf32.f32 "
                        "{%0,%1,%2,%3},{%4,%5,%6,%7},{%8,%9},{%0,%1,%2,%3};"
                        : "+f"(acc[mt][nt][0]), "+f"(acc[mt][nt][1]),
                          "+f"(acc[mt][nt][2]), "+f"(acc[mt][nt][3])
                        : "r"(a[mt][0]), "r"(a[mt][1]), "r"(a[mt][2]), "r"(a[mt][3]),
                          "r"(b[nt][0]), "r"(b[nt][1]));
                }
        }
    };

    stage(0, 0);
    stage(1, 16);
#pragma unroll
    for (int i = 0; i < 8; i++) {
        if (i < 7) asm volatile("cp.async.wait_group 1;");
        else       asm volatile("cp.async.wait_group 0;");
        __syncthreads();
        compute(i & 1, i * 16);
        __syncthreads();
        if (i + 2 < 8) stage(i & 1, (i + 2) * 16);
    }

    // epilogue: store C (+ optional att dots)
#pragma unroll
    for (int mt = 0; mt < 2; mt++) {
#pragma unroll
        for (int h = 0; h < 2; h++) {
            int row = row0 + wm * 32 + mt * 16 + h * 8 + gp;
            bool ok = (row < NN);
            float ps = 0.f, pd = 0.f;
#pragma unroll
            for (int nt = 0; nt < 8; nt++) {
                int col = wn * 64 + nt * 8 + 2 * qi;
                float c0 = acc[mt][nt][2 * h], c1 = acc[mt][nt][2 * h + 1];
                if (ok) *(float2*)&g_tmp[row * 128 + col] = make_float2(c0, c1);
                if (ATT) {
                    ps = fmaf(c0, s_as[col], fmaf(c1, s_as[col + 1], ps));
                    pd = fmaf(c0, s_ad[col], fmaf(c1, s_ad[col + 1], pd));
                }
            }
            if (ATT) {
                ps += __shfl_xor_sync(0xffffffffu, ps, 1);
                ps += __shfl_xor_sync(0xffffffffu, ps, 2);
                pd += __shfl_xor_sync(0xffffffffu, pd, 1);
                pd += __shfl_xor_sync(0xffffffffu, pd, 2);
                if (qi == 0 && ok) {
                    atomicAdd(&g_als[row], ps);
                    atomicAdd(&g_ald[row], pd);
                }
            }
        }
    }
}

// ---------------- fused BN stats + last-block finalize ----------------
__device__ __forceinline__ void stats_and_finalize(
    float4 acc, int w, int l,
    const float* __restrict__ gamma, const float* __restrict__ beta,
    float (*ss)[128], float (*sq)[128]) {
    *(float4*)&ss[w][l * 4] = acc;
    *(float4*)&sq[w][l * 4] = make_float4(acc.x * acc.x, acc.y * acc.y,
                                          acc.z * acc.z, acc.w * acc.w);
    __syncthreads();
    int t = threadIdx.x;
    if (t < 128) {
        float S = 0.f, Q = 0.f;
#pragma unroll
        for (int ww = 0; ww < 8; ww++) { S += ss[ww][t]; Q += sq[ww][t]; }
        int stripe = (blockIdx.x & (NSTRIPE - 1)) * 128 + t;
        atomicAdd(&g_pS[stripe], S);
        atomicAdd(&g_pQ[stripe], Q);
    }
    __threadfence();
    __shared__ unsigned int s_last;
    __syncthreads();
    if (t == 0)
        s_last = (atomicAdd(&g_ticket, 1u) == (unsigned)(gridDim.x - 1)) ? 1u : 0u;
    __syncthreads();
    if (s_last) {
        if (t < 128) {
            double S = 0.0, Q = 0.0;
            for (int s = 0; s < NSTRIPE; s++) {
                S += (double)__ldcg(&g_pS[s * 128 + t]);
                Q += (double)__ldcg(&g_pQ[s * 128 + t]);
            }
            double mu = S / (double)NN;
            double var = Q / (double)NN - mu * mu;
            float vf = (float)var; if (vf < 0.f) vf = 0.f;
            float sc = gamma[t] * rsqrtf(vf + EPSF);
            g_scale[t] = sc;
            g_shift[t] = beta[t] - (float)mu * sc;
        }
        __syncthreads();
        for (int i = t; i < NSTRIPE * HH; i += blockDim.x) {
            g_pS[i] = 0.f; g_pQ[i] = 0.f;
        }
        if (t == 0) g_ticket = 0u;
    }
}

// ---------------- GCN segment aggregation ----------------
template<bool ZATT>
__global__ void k_gcn_seg(const float* __restrict__ bias,
                          const float* __restrict__ gamma,
                          const float* __restrict__ beta) {
    __shared__ float ss[8][128], sq[8][128];
    int w = threadIdx.x >> 5, l = threadIdx.x & 31;
    int d = blockIdx.x * 8 + w;            // NN = 50000 = 6250*8, always in range
    float dd = g_dis[d];
    float4 b4 = ((const float4*)bias)[l];
    float4 self = ((const float4*)&g_tmp[d * HH])[l];
    float dd2 = dd * dd;
    float4 acc = make_float4(fmaf(self.x, dd2, b4.x), fmaf(self.y, dd2, b4.y),
                             fmaf(self.z, dd2, b4.z), fmaf(self.w, dd2, b4.w));
    int deg = min(g_deg[d], BCAP);
    const int* bkt = &g_bkt[d * BCAP];
#pragma unroll 4
    for (int j = 0; j < deg; j++) {
        int s = bkt[j];
        float nrm = g_dis[s] * dd;
        float4 v = ((const float4*)&g_tmp[s * HH])[l];
        acc.x = fmaf(v.x, nrm, acc.x); acc.y = fmaf(v.y, nrm, acc.y);
        acc.z = fmaf(v.z, nrm, acc.z); acc.w = fmaf(v.w, nrm, acc.w);
    }
    ((float4*)&g_acc[d * HH])[l] = acc;
    if (ZATT && l == 0) { g_als[d] = 0.f; g_ald[d] = 0.f; }
    stats_and_finalize(acc, w, l, gamma, beta, ss, sq);
}

// ---------------- GAT softmax + aggregation ----------------
__global__ void k_gat_seg(const float* __restrict__ bias,
                          const float* __restrict__ gamma,
                          const float* __restrict__ beta) {
    __shared__ float ss[8][128], sq[8][128];
    int w = threadIdx.x >> 5, l = threadIdx.x & 31;
    int d = blockIdx.x * 8 + w;
    float ald_d = g_ald[d];
    float self_e = lrelu(g_als[d] + ald_d);
    int deg = min(g_deg[d], BCAP);
    const int* bkt = &g_bkt[d * BCAP];
    float m = self_e;
    for (int j = l; j < deg; j += 32)
        m = fmaxf(m, lrelu(g_als[bkt[j]] + ald_d));
#pragma unroll
    for (int o = 16; o; o >>= 1) m = fmaxf(m, __shfl_xor_sync(0xffffffffu, m, o));
    float den = 0.f;
    for (int j = l; j < deg; j += 32)
        den += expf(lrelu(g_als[bkt[j]] + ald_d) - m);
#pragma unroll
    for (int o = 16; o; o >>= 1) den += __shfl_xor_sync(0xffffffffu, den, o);
    den += expf(self_e - m);
    float rden = 1.0f / den;
    float4 b4 = ((const float4*)bias)[l];
    float a_self = expf(self_e - m) * rden;
    float4 self = ((const float4*)&g_tmp[d * HH])[l];
    float4 acc = make_float4(fmaf(self.x, a_self, b4.x), fmaf(self.y, a_self, b4.y),
                             fmaf(self.z, a_self, b4.z), fmaf(self.w, a_self, b4.w));
#pragma unroll 2
    for (int j = 0; j < deg; j++) {
        int s = bkt[j];
        float al = expf(lrelu(g_als[s] + ald_d) - m) * rden;
        float4 v = ((const float4*)&g_tmp[s * HH])[l];
        acc.x = fmaf(v.x, al, acc.x); acc.y = fmaf(v.y, al, acc.y);
        acc.z = fmaf(v.z, al, acc.z); acc.w = fmaf(v.w, al, acc.w);
    }
    ((float4*)&g_acc[d * HH])[l] = acc;
    stats_and_finalize(acc, w, l, gamma, beta, ss, sq);
}

// ---------------- pooling (BN3+ReLU fused) + MLP ----------------
__global__ void k_pool_scatter(const int* __restrict__ batch) {
    int w = (blockIdx.x * blockDim.x + threadIdx.x) >> 5;
    if (w >= NN) return;
    int l = threadIdx.x & 31;
    int b = batch[w];
    if (!l) atomicAdd(&g_cnt[b], 1.0f);
    float4 v = ((const float4*)&g_acc[w * HH])[l];
    float4 sc = ((const float4*)g_scale)[l];
    float4 sh = ((const float4*)g_shift)[l];
    v.x = fmaxf(fmaf(v.x, sc.x, sh.x), 0.f);
    v.y = fmaxf(fmaf(v.y, sc.y, sh.y), 0.f);
    v.z = fmaxf(fmaf(v.z, sc.z, sh.z), 0.f);
    v.w = fmaxf(fmaf(v.w, sc.w, sh.w), 0.f);
    red_add_f4(&g_pooled[b * HH + l * 4], v);
}
__global__ void k_mlp(const float* __restrict__ fw1, const float* __restrict__ fb1,
                      const float* __restrict__ fw2, const float* __restrict__ fb2,
                      float* __restrict__ out) {
    __shared__ float p[HH], z[HH], r[4];
    int g = blockIdx.x, t = threadIdx.x;
    float inv = 1.0f / fmaxf(g_cnt[g], 1.0f);
    p[t] = g_pooled[g * HH + t] * inv;
    __syncthreads();
    float s = fb1[t];
#pragma unroll 8
    for (int k = 0; k < HH; k++) s = fmaf(p[k], fw1[k * HH + t], s);
    z[t] = fmaxf(s, 0.f);
    __syncthreads();
    float v = z[t] * fw2[t];
#pragma unroll
    for (int o = 16; o; o >>= 1) v += __shfl_xor_sync(0xffffffffu, v, o);
    if ((t & 31) == 0) r[t >> 5] = v;
    __syncthreads();
    if (t == 0) out[g] = r[0] + r[1] + r[2] + r[3] + fb2[0];
}

// ---------------- launch ----------------
extern "C" void kernel_launch(void* const* d_in, const int* in_sizes, int n_in,
                              void* d_out, int out_size) {
    const float* x       = (const float*)d_in[0];
    const int*   ei      = (const int*)d_in[1];
    const int*   batch   = (const int*)d_in[2];
    const float* W1      = (const float*)d_in[3];
    const float* b1      = (const float*)d_in[4];
    const float* g1      = (const float*)d_in[5];
    const float* be1     = (const float*)d_in[6];
    const float* Wg      = (const float*)d_in[7];
    const float* att_src = (const float*)d_in[8];
    const float* att_dst = (const float*)d_in[9];
    const float* bg      = (const float*)d_in[10];
    const float* g2      = (const float*)d_in[11];
    const float* be2     = (const float*)d_in[12];
    const float* W3      = (const float*)d_in[13];
    const float* b3      = (const float*)d_in[14];
    const float* g3      = (const float*)d_in[15];
    const float* be3     = (const float*)d_in[16];
    const float* fw1     = (const float*)d_in[17];
    const float* fb1     = (const float*)d_in[18];
    const float* fw2     = (const float*)d_in[19];
    const float* fb2     = (const float*)d_in[20];
    float* out = (float*)d_out;

    const int* src = ei;
    const int* dst = ei + EE;

    const int NB   = (NN + 255) / 256;
    const int EB   = (EE + 255) / 256;
    const int NWB  = (NN * 32 + 255) / 256;
    const int SEGB = NN / 8;                  // 6250 (exact)
    const int GEMB = (NN + 127) / 128;        // 391

    // graph structure
    k_zero<<<NB, 256>>>();
    k_fill<<<EB, 256>>>(src, dst);
    k_dis<<<NB, 256>>>();

    // ---- layer 1: GCN ----
    k_gemm<false, false><<<GEMB, 256>>>(x, W1, nullptr, nullptr);
    k_gcn_seg<true><<<SEGB, 256>>>(b1, g1, be1);      // + BN1 finalize, zero att

    // ---- layer 2: GAT (BN1 fused into GEMM; att dots in epilogue) ----
    k_gemm<true, true><<<GEMB, 256>>>(nullptr, Wg, att_src, att_dst);
    k_gat_seg<<<SEGB, 256>>>(bg, g2, be2);            // + BN2 finalize

    // ---- layer 3: GCN (BN2 fused into GEMM) ----
    k_gemm<true, false><<<GEMB, 256>>>(nullptr, W3, nullptr, nullptr);
    k_gcn_seg<false><<<SEGB, 256>>>(b3, g3, be3);     // + BN3 finalize

    // ---- pool (BN3+ReLU fused) + MLP ----
    k_pool_scatter<<<NWB, 256>>>(batch);
    k_mlp<<<GG, 128>>>(fw1, fb1, fw2, fb2, out);
}

// round 5
// speedup vs baseline: 1.0814x; 1.0814x over previous
#include <cuda_runtime.h>
#include <math.h>
#include <stdint.h>

// ---------------- problem constants ----------------
#define NN 50000
#define EE 600000
#define HH 128
#define GG 256
#define EPSF 1e-5f
#define SLOPE 0.2f
#define NSTRIPE 64
#define BCAP 64            // bucket capacity per node (Poisson(12) => P(>64) ~ 0)

// ---------------- scratch ----------------
__device__ __align__(16) float g_tmp[NN * HH];   // GEMM output
__device__ __align__(16) float g_acc[NN * HH];   // aggregated pre-BN activations
__device__ float g_dis[NN];
__device__ float g_als[NN], g_ald[NN];
__device__ int   g_deg[NN];
__device__ int   g_bkt[NN * BCAP];               // direct-bucket CSR
__device__ float g_pS[NSTRIPE * HH], g_pQ[NSTRIPE * HH];
__device__ __align__(16) float g_scale[HH], g_shift[HH];
__device__ __align__(16) float g_pooled[GG * HH];
__device__ float g_cnt[GG];

__device__ __forceinline__ float lrelu(float x) { return x > 0.f ? x : SLOPE * x; }

__device__ __forceinline__ float to_tf32(float x) {
    float r;
    asm("cvt.rna.tf32.f32 %0, %1;" : "=f"(r) : "f"(x));
    return r;
}

__device__ __forceinline__ void red_add_f4(float* p, float4 v) {
    asm volatile("red.global.add.v4.f32 [%0], {%1,%2,%3,%4};"
                 :: "l"(__cvta_generic_to_global(p)),
                    "f"(v.x), "f"(v.y), "f"(v.z), "f"(v.w)
                 : "memory");
}

// ---------------- zero + bucket CSR build ----------------
__global__ void k_zero() {
    int i = blockIdx.x * blockDim.x + threadIdx.x;
    if (i < NN) g_deg[i] = 0;
    if (i < GG) g_cnt[i] = 0.f;
    if (i < GG * HH) g_pooled[i] = 0.f;
    if (i < NSTRIPE * HH) { g_pS[i] = 0.f; g_pQ[i] = 0.f; }
}
__global__ void k_fill(const int* __restrict__ src, const int* __restrict__ dst) {
    int e = blockIdx.x * blockDim.x + threadIdx.x;
    if (e >= EE) return;
    int d = dst[e];
    int pos = atomicAdd(&g_deg[d], 1);
    if (pos < BCAP) g_bkt[d * BCAP + pos] = src[e];
}
__global__ void k_dis() {
    int i = blockIdx.x * blockDim.x + threadIdx.x;
    if (i < NN) g_dis[i] = rsqrtf(1.0f + (float)g_deg[i]);
}

// ---------------- TF32 tensor-core GEMM, cp.async 2-stage pipeline ----------
template<bool BN, bool ATT>
__global__ __launch_bounds__(256, 2)
void k_gemm(const float* __restrict__ Aext, const float* __restrict__ W,
            const float* __restrict__ av_s, const float* __restrict__ av_d) {
    __shared__ float As[2][128][20];     // [stage][row][k] raw fp32, k-chunk=16
    __shared__ float Bs[2][16][136];     // [stage][k][n]   raw fp32
    __shared__ float s_sc[128], s_sh[128], s_as[128], s_ad[128];
    const float* A = BN ? (const float*)g_acc : Aext;
    int t = threadIdx.x;
    if (t < 128) {
        if (BN)  { s_sc[t] = g_scale[t]; s_sh[t] = g_shift[t]; }
        if (ATT) { s_as[t] = av_s[t];    s_ad[t] = av_d[t]; }
    }
    int row0 = blockIdx.x * 128;
    int warpId = t >> 5, lane = t & 31;
    int wm = warpId >> 1, wn = warpId & 1;   // 4 x 2 warp grid
    int gp = lane >> 2, qi = lane & 3;

    int arow = t >> 2;            // 0..63 (two passes of 64 rows)
    int ac4  = (t & 3) * 4;       // 0,4,8,12
    int brow = t >> 5;            // 0..7  (two passes of 8 rows)
    int bc4  = (t & 31) * 4;

    float acc[2][8][4];
#pragma unroll
    for (int mt = 0; mt < 2; mt++)
#pragma unroll
        for (int nt = 0; nt < 8; nt++)
#pragma unroll
            for (int j = 0; j < 4; j++) acc[mt][nt][j] = 0.f;

    auto stage = [&](int st, int kt) {
#pragma unroll
        for (int p = 0; p < 2; p++) {
            int r = p * 64 + arow;
            int grow = row0 + r;
            uint32_t sa = (uint32_t)__cvta_generic_to_shared(&As[st][r][ac4]);
            const float* gp_ = &A[(size_t)grow * 128 + kt + ac4];
            int sz = (grow < NN) ? 16 : 0;
            asm volatile("cp.async.cg.shared.global [%0], [%1], 16, %2;"
                         :: "r"(sa), "l"(gp_), "r"(sz));
        }
#pragma unroll
        for (int p = 0; p < 2; p++) {
            int r = p * 8 + brow;
            uint32_t sa = (uint32_t)__cvta_generic_to_shared(&Bs[st][r][bc4]);
            const float* gp_ = &W[(kt + r) * 128 + bc4];
            asm volatile("cp.async.cg.shared.global [%0], [%1], 16, 16;"
                         :: "r"(sa), "l"(gp_));
        }
        asm volatile("cp.async.commit_group;");
    };

    auto compute = [&](int st, int kt) {
#pragma unroll
        for (int k8 = 0; k8 < 16; k8 += 8) {
            float sc0 = 0.f, sh0 = 0.f, sc4 = 0.f, sh4 = 0.f;
            if (BN) {
                sc0 = s_sc[kt + k8 + qi];     sh0 = s_sh[kt + k8 + qi];
                sc4 = s_sc[kt + k8 + qi + 4]; sh4 = s_sh[kt + k8 + qi + 4];
            }
            uint32_t a[2][4], b[8][2];
#pragma unroll
            for (int mt = 0; mt < 2; mt++) {
                int rb = wm * 32 + mt * 16 + gp;
                float a0 = As[st][rb][k8 + qi],     a1 = As[st][rb + 8][k8 + qi];
                float a2 = As[st][rb][k8 + qi + 4], a3 = As[st][rb + 8][k8 + qi + 4];
                if (BN) {
                    a0 = fmaxf(fmaf(a0, sc0, sh0), 0.f);
                    a1 = fmaxf(fmaf(a1, sc0, sh0), 0.f);
                    a2 = fmaxf(fmaf(a2, sc4, sh4), 0.f);
                    a3 = fmaxf(fmaf(a3, sc4, sh4), 0.f);
                }
                a[mt][0] = __float_as_uint(to_tf32(a0));
                a[mt][1] = __float_as_uint(to_tf32(a1));
                a[mt][2] = __float_as_uint(to_tf32(a2));
                a[mt][3] = __float_as_uint(to_tf32(a3));
            }
#pragma unroll
            for (int nt = 0; nt < 8; nt++) {
                int cb = wn * 64 + nt * 8 + gp;
                b[nt][0] = __float_as_uint(to_tf32(Bs[st][k8 + qi][cb]));
                b[nt][1] = __float_as_uint(to_tf32(Bs[st][k8 + qi + 4][cb]));
            }
#pragma unroll
            for (int mt = 0; mt < 2; mt++)
#pragma unroll
                for (int nt = 0; nt < 8; nt++) {
                    asm volatile(
                        "mma.sync.aligned.m16n8k8.row.col.f32.tf32.tf32.f32 "
                        "{%0,%1,%2,%3},{%4,%5,%6,%7},{%8,%9},{%0,%1,%2,%3};"
                        : "+f"(acc[mt][nt][0]), "+f"(acc[mt][nt][1]),
                          "+f"(acc[mt][nt][2]), "+f"(acc[mt][nt][3])
                        : "r"(a[mt][0]), "r"(a[mt][1]), "r"(a[mt][2]), "r"(a[mt][3]),
                          "r"(b[nt][0]), "r"(b[nt][1]));
                }
        }
    };

    stage(0, 0);
    stage(1, 16);
#pragma unroll
    for (int i = 0; i < 8; i++) {
        if (i < 7) asm volatile("cp.async.wait_group 1;");
        else       asm volatile("cp.async.wait_group 0;");
        __syncthreads();
        compute(i & 1, i * 16);
        __syncthreads();
        if (i + 2 < 8) stage(i & 1, (i + 2) * 16);
    }

    // epilogue: store C (+ optional att dots)
#pragma unroll
    for (int mt = 0; mt < 2; mt++) {
#pragma unroll
        for (int h = 0; h < 2; h++) {
            int row = row0 + wm * 32 + mt * 16 + h * 8 + gp;
            bool ok = (row < NN);
            float ps = 0.f, pd = 0.f;
#pragma unroll
            for (int nt = 0; nt < 8; nt++) {
                int col = wn * 64 + nt * 8 + 2 * qi;
                float c0 = acc[mt][nt][2 * h], c1 = acc[mt][nt][2 * h + 1];
                if (ok) *(float2*)&g_tmp[row * 128 + col] = make_float2(c0, c1);
                if (ATT) {
                    ps = fmaf(c0, s_as[col], fmaf(c1, s_as[col + 1], ps));
                    pd = fmaf(c0, s_ad[col], fmaf(c1, s_ad[col + 1], pd));
                }
            }
            if (ATT) {
                ps += __shfl_xor_sync(0xffffffffu, ps, 1);
                ps += __shfl_xor_sync(0xffffffffu, ps, 2);
                pd += __shfl_xor_sync(0xffffffffu, pd, 1);
                pd += __shfl_xor_sync(0xffffffffu, pd, 2);
                if (qi == 0 && ok) {
                    atomicAdd(&g_als[row], ps);
                    atomicAdd(&g_ald[row], pd);
                }
            }
        }
    }
}

// ---------------- shared stats accumulation (no fence, no ticket) ----------
__device__ __forceinline__ void stats_stripe(
    float4 acc, int w, int l, float (*ss)[128], float (*sq)[128]) {
    *(float4*)&ss[w][l * 4] = acc;
    *(float4*)&sq[w][l * 4] = make_float4(acc.x * acc.x, acc.y * acc.y,
                                          acc.z * acc.z, acc.w * acc.w);
    __syncthreads();
    int t = threadIdx.x;
    if (t < 128) {
        float S = 0.f, Q = 0.f;
#pragma unroll
        for (int ww = 0; ww < 8; ww++) { S += ss[ww][t]; Q += sq[ww][t]; }
        int stripe = (blockIdx.x & (NSTRIPE - 1)) * 128 + t;
        atomicAdd(&g_pS[stripe], S);
        atomicAdd(&g_pQ[stripe], Q);
    }
}

// ---------------- GCN segment aggregation ----------------
template<bool ZATT>
__global__ void k_gcn_seg(const float* __restrict__ bias) {
    __shared__ float ss[8][128], sq[8][128];
    int w = threadIdx.x >> 5, l = threadIdx.x & 31;
    int d = blockIdx.x * 8 + w;            // NN = 50000 = 6250*8, always in range
    float dd = g_dis[d];
    float4 b4 = ((const float4*)bias)[l];
    float4 self = ((const float4*)&g_tmp[d * HH])[l];
    float dd2 = dd * dd;
    float4 acc = make_float4(fmaf(self.x, dd2, b4.x), fmaf(self.y, dd2, b4.y),
                             fmaf(self.z, dd2, b4.z), fmaf(self.w, dd2, b4.w));
    int deg = min(g_deg[d], BCAP);
    const int* bkt = &g_bkt[d * BCAP];
#pragma unroll 4
    for (int j = 0; j < deg; j++) {
        int s = __ldg(&bkt[j]);
        float nrm = g_dis[s] * dd;
        float4 v = ((const float4*)&g_tmp[s * HH])[l];
        acc.x = fmaf(v.x, nrm, acc.x); acc.y = fmaf(v.y, nrm, acc.y);
        acc.z = fmaf(v.z, nrm, acc.z); acc.w = fmaf(v.w, nrm, acc.w);
    }
    ((float4*)&g_acc[d * HH])[l] = acc;
    if (ZATT && l == 0) { g_als[d] = 0.f; g_ald[d] = 0.f; }
    stats_stripe(acc, w, l, ss, sq);
}

// ---------------- GAT softmax + aggregation ----------------
__global__ void k_gat_seg(const float* __restrict__ bias) {
    __shared__ float ss[8][128], sq[8][128];
    int w = threadIdx.x >> 5, l = threadIdx.x & 31;
    int d = blockIdx.x * 8 + w;
    float ald_d = g_ald[d];
    float self_e = lrelu(g_als[d] + ald_d);
    int deg = min(g_deg[d], BCAP);
    const int* bkt = &g_bkt[d * BCAP];
    float m = self_e;
    for (int j = l; j < deg; j += 32)
        m = fmaxf(m, lrelu(g_als[__ldg(&bkt[j])] + ald_d));
#pragma unroll
    for (int o = 16; o; o >>= 1) m = fmaxf(m, __shfl_xor_sync(0xffffffffu, m, o));
    float den = 0.f;
    for (int j = l; j < deg; j += 32)
        den += expf(lrelu(g_als[__ldg(&bkt[j])] + ald_d) - m);
#pragma unroll
    for (int o = 16; o; o >>= 1) den += __shfl_xor_sync(0xffffffffu, den, o);
    den += expf(self_e - m);
    float rden = 1.0f / den;
    float4 b4 = ((const float4*)bias)[l];
    float a_self = expf(self_e - m) * rden;
    float4 self = ((const float4*)&g_tmp[d * HH])[l];
    float4 acc = make_float4(fmaf(self.x, a_self, b4.x), fmaf(self.y, a_self, b4.y),
                             fmaf(self.z, a_self, b4.z), fmaf(self.w, a_self, b4.w));
#pragma unroll 2
    for (int j = 0; j < deg; j++) {
        int s = __ldg(&bkt[j]);
        float al = expf(lrelu(g_als[s] + ald_d) - m) * rden;
        float4 v = ((const float4*)&g_tmp[s * HH])[l];
        acc.x = fmaf(v.x, al, acc.x); acc.y = fmaf(v.y, al, acc.y);
        acc.z = fmaf(v.z, al, acc.z); acc.w = fmaf(v.w, al, acc.w);
    }
    ((float4*)&g_acc[d * HH])[l] = acc;
    stats_stripe(acc, w, l, ss, sq);
}

// ---------------- BN finalize (1 block; reads stripes, re-zeros them) ------
__global__ void k_bn_prep(const float* __restrict__ gamma, const float* __restrict__ beta) {
    int c = threadIdx.x;               // 128 threads
    double S = 0.0, Q = 0.0;
    for (int s = 0; s < NSTRIPE; s++) {
        S += (double)g_pS[s * 128 + c];
        Q += (double)g_pQ[s * 128 + c];
        g_pS[s * 128 + c] = 0.f;
        g_pQ[s * 128 + c] = 0.f;
    }
    double mu = S / (double)NN;
    double var = Q / (double)NN - mu * mu;
    float vf = (float)var; if (vf < 0.f) vf = 0.f;
    float sc = gamma[c] * rsqrtf(vf + EPSF);
    g_scale[c] = sc;
    g_shift[c] = beta[c] - (float)mu * sc;
}

// ---------------- pooling (BN3+ReLU fused) + MLP ----------------
__global__ void k_pool_scatter(const int* __restrict__ batch) {
    int w = (blockIdx.x * blockDim.x + threadIdx.x) >> 5;
    if (w >= NN) return;
    int l = threadIdx.x & 31;
    int b = batch[w];
    if (!l) atomicAdd(&g_cnt[b], 1.0f);
    float4 v = ((const float4*)&g_acc[w * HH])[l];
    float4 sc = ((const float4*)g_scale)[l];
    float4 sh = ((const float4*)g_shift)[l];
    v.x = fmaxf(fmaf(v.x, sc.x, sh.x), 0.f);
    v.y = fmaxf(fmaf(v.y, sc.y, sh.y), 0.f);
    v.z = fmaxf(fmaf(v.z, sc.z, sh.z), 0.f);
    v.w = fmaxf(fmaf(v.w, sc.w, sh.w), 0.f);
    red_add_f4(&g_pooled[b * HH + l * 4], v);
}
__global__ void k_mlp(const float* __restrict__ fw1, const float* __restrict__ fb1,
                      const float* __restrict__ fw2, const float* __restrict__ fb2,
                      float* __restrict__ out) {
    __shared__ float p[HH], z[HH], r[4];
    int g = blockIdx.x, t = threadIdx.x;
    float inv = 1.0f / fmaxf(g_cnt[g], 1.0f);
    p[t] = g_pooled[g * HH + t] * inv;
    __syncthreads();
    float s = fb1[t];
#pragma unroll 8
    for (int k = 0; k < HH; k++) s = fmaf(p[k], fw1[k * HH + t], s);
    z[t] = fmaxf(s, 0.f);
    __syncthreads();
    float v = z[t] * fw2[t];
#pragma unroll
    for (int o = 16; o; o >>= 1) v += __shfl_xor_sync(0xffffffffu, v, o);
    if ((t & 31) == 0) r[t >> 5] = v;
    __syncthreads();
    if (t == 0) out[g] = r[0] + r[1] + r[2] + r[3] + fb2[0];
}

// ---------------- launch ----------------
extern "C" void kernel_launch(void* const* d_in, const int* in_sizes, int n_in,
                              void* d_out, int out_size) {
    const float* x       = (const float*)d_in[0];
    const int*   ei      = (const int*)d_in[1];
    const int*   batch   = (const int*)d_in[2];
    const float* W1      = (const float*)d_in[3];
    const float* b1      = (const float*)d_in[4];
    const float* g1      = (const float*)d_in[5];
    const float* be1     = (const float*)d_in[6];
    const float* Wg      = (const float*)d_in[7];
    const float* att_src = (const float*)d_in[8];
    const float* att_dst = (const float*)d_in[9];
    const float* bg      = (const float*)d_in[10];
    const float* g2      = (const float*)d_in[11];
    const float* be2     = (const float*)d_in[12];
    const float* W3      = (const float*)d_in[13];
    const float* b3      = (const float*)d_in[14];
    const float* g3      = (const float*)d_in[15];
    const float* be3     = (const float*)d_in[16];
    const float* fw1     = (const float*)d_in[17];
    const float* fb1     = (const float*)d_in[18];
    const float* fw2     = (const float*)d_in[19];
    const float* fb2     = (const float*)d_in[20];
    float* out = (float*)d_out;

    const int* src = ei;
    const int* dst = ei + EE;

    const int NB   = (NN + 255) / 256;
    const int EB   = (EE + 255) / 256;
    const int NWB  = (NN * 32 + 255) / 256;
    const int SEGB = NN / 8;                  // 6250 (exact)
    const int GEMB = (NN + 127) / 128;        // 391

    // graph structure
    k_zero<<<NB, 256>>>();
    k_fill<<<EB, 256>>>(src, dst);
    k_dis<<<NB, 256>>>();

    // ---- layer 1: GCN ----
    k_gemm<false, false><<<GEMB, 256>>>(x, W1, nullptr, nullptr);
    k_gcn_seg<true><<<SEGB, 256>>>(b1);               // + zero att accumulators
    k_bn_prep<<<1, 128>>>(g1, be1);

    // ---- layer 2: GAT (BN1 fused into GEMM; att dots in epilogue) ----
    k_gemm<true, true><<<GEMB, 256>>>(nullptr, Wg, att_src, att_dst);
    k_gat_seg<<<SEGB, 256>>>(bg);
    k_bn_prep<<<1, 128>>>(g2, be2);

    // ---- layer 3: GCN (BN2 fused into GEMM) ----
    k_gemm<true, false><<<GEMB, 256>>>(nullptr, W3, nullptr, nullptr);
    k_gcn_seg<false><<<SEGB, 256>>>(b3);
    k_bn_prep<<<1, 128>>>(g3, be3);

    // ---- pool (BN3+ReLU fused) + MLP ----
    k_pool_scatter<<<NWB, 256>>>(batch);
    k_mlp<<<GG, 128>>>(fw1, fb1, fw2, fb2, out);
}

// round 6
// speedup vs baseline: 1.1150x; 1.0311x over previous
#include <cuda_runtime.h>
#include <cuda_fp16.h>
#include <math.h>
#include <stdint.h>

// ---------------- problem constants ----------------
#define NN 50000
#define EE 600000
#define HH 128
#define GG 256
#define EPSF 1e-5f
#define SLOPE 0.2f
#define NSTRIPE 64
#define BCAP 64            // bucket capacity per node (Poisson(12) => P(>64) ~ 0)

// ---------------- scratch ----------------
__device__ __align__(16) __half2 g_tmp[NN * (HH / 2)];  // GEMM output, fp16 payload
__device__ __align__(16) float g_acc[NN * HH];          // aggregated pre-BN activations
__device__ float g_dis[NN];
__device__ float g_als[NN], g_ald[NN];
__device__ int   g_deg[NN];
__device__ int   g_bkt[NN * BCAP];               // direct-bucket CSR
__device__ float g_pS[NSTRIPE * HH], g_pQ[NSTRIPE * HH];
__device__ __align__(16) float g_scale[HH], g_shift[HH];
__device__ __align__(16) float g_pooled[GG * HH];
__device__ float g_cnt[GG];

__device__ __forceinline__ float lrelu(float x) { return x > 0.f ? x : SLOPE * x; }

__device__ __forceinline__ float to_tf32(float x) {
    float r;
    asm("cvt.rna.tf32.f32 %0, %1;" : "=f"(r) : "f"(x));
    return r;
}

__device__ __forceinline__ void red_add_f4(float* p, float4 v) {
    asm volatile("red.global.add.v4.f32 [%0], {%1,%2,%3,%4};"
                 :: "l"(__cvta_generic_to_global(p)),
                    "f"(v.x), "f"(v.y), "f"(v.z), "f"(v.w)
                 : "memory");
}

// gather 4 floats (cols 4l..4l+3) of node s from fp16 payload
__device__ __forceinline__ float4 load_row4(int s, int l) {
    uint2 u = *(const uint2*)&g_tmp[s * (HH / 2) + l * 2];
    float2 f0 = __half22float2(*(__half2*)&u.x);
    float2 f1 = __half22float2(*(__half2*)&u.y);
    return make_float4(f0.x, f0.y, f1.x, f1.y);
}

// ---------------- zero + bucket CSR build ----------------
__global__ void k_zero() {
    int i = blockIdx.x * blockDim.x + threadIdx.x;
    if (i < NN) g_deg[i] = 0;
    if (i < GG) g_cnt[i] = 0.f;
    if (i < GG * HH) g_pooled[i] = 0.f;
    if (i < NSTRIPE * HH) { g_pS[i] = 0.f; g_pQ[i] = 0.f; }
}
__global__ void k_fill(const int* __restrict__ src, const int* __restrict__ dst) {
    int e = blockIdx.x * blockDim.x + threadIdx.x;
    if (e >= EE) return;
    int d = dst[e];
    int pos = atomicAdd(&g_deg[d], 1);
    if (pos < BCAP) g_bkt[d * BCAP + pos] = src[e];
}
__global__ void k_dis() {
    int i = blockIdx.x * blockDim.x + threadIdx.x;
    if (i < NN) g_dis[i] = rsqrtf(1.0f + (float)g_deg[i]);
}

// ---------------- TF32 tensor-core GEMM, cp.async 2-stage pipeline ----------
// C (fp16) = A[n,128] @ W[128,128]; A fp32 (ext or g_acc with BN+ReLU).
template<bool BN, bool ATT>
__global__ __launch_bounds__(256, 2)
void k_gemm(const float* __restrict__ Aext, const float* __restrict__ W,
            const float* __restrict__ av_s, const float* __restrict__ av_d) {
    __shared__ float As[2][128][20];     // [stage][row][k] raw fp32, k-chunk=16
    __shared__ float Bs[2][16][136];     // [stage][k][n]   raw fp32
    __shared__ float s_sc[128], s_sh[128], s_as[128], s_ad[128];
    const float* A = BN ? (const float*)g_acc : Aext;
    int t = threadIdx.x;
    if (t < 128) {
        if (BN)  { s_sc[t] = g_scale[t]; s_sh[t] = g_shift[t]; }
        if (ATT) { s_as[t] = av_s[t];    s_ad[t] = av_d[t]; }
    }
    int row0 = blockIdx.x * 128;
    int warpId = t >> 5, lane = t & 31;
    int wm = warpId >> 1, wn = warpId & 1;   // 4 x 2 warp grid
    int gp = lane >> 2, qi = lane & 3;

    int arow = t >> 2;            // 0..63 (two passes of 64 rows)
    int ac4  = (t & 3) * 4;       // 0,4,8,12
    int brow = t >> 5;            // 0..7  (two passes of 8 rows)
    int bc4  = (t & 31) * 4;

    float acc[2][8][4];
#pragma unroll
    for (int mt = 0; mt < 2; mt++)
#pragma unroll
        for (int nt = 0; nt < 8; nt++)
#pragma unroll
            for (int j = 0; j < 4; j++) acc[mt][nt][j] = 0.f;

    auto stage = [&](int st, int kt) {
#pragma unroll
        for (int p = 0; p < 2; p++) {
            int r = p * 64 + arow;
            int grow = row0 + r;
            uint32_t sa = (uint32_t)__cvta_generic_to_shared(&As[st][r][ac4]);
            const float* gp_ = &A[(size_t)grow * 128 + kt + ac4];
            int sz = (grow < NN) ? 16 : 0;
            asm volatile("cp.async.cg.shared.global [%0], [%1], 16, %2;"
                         :: "r"(sa), "l"(gp_), "r"(sz));
        }
#pragma unroll
        for (int p = 0; p < 2; p++) {
            int r = p * 8 + brow;
            uint32_t sa = (uint32_t)__cvta_generic_to_shared(&Bs[st][r][bc4]);
            const float* gp_ = &W[(kt + r) * 128 + bc4];
            asm volatile("cp.async.cg.shared.global [%0], [%1], 16, 16;"
                         :: "r"(sa), "l"(gp_));
        }
        asm volatile("cp.async.commit_group;");
    };

    auto compute = [&](int st, int kt) {
#pragma unroll
        for (int k8 = 0; k8 < 16; k8 += 8) {
            float sc0 = 0.f, sh0 = 0.f, sc4 = 0.f, sh4 = 0.f;
            if (BN) {
                sc0 = s_sc[kt + k8 + qi];     sh0 = s_sh[kt + k8 + qi];
                sc4 = s_sc[kt + k8 + qi + 4]; sh4 = s_sh[kt + k8 + qi + 4];
            }
            uint32_t a[2][4], b[8][2];
#pragma unroll
            for (int mt = 0; mt < 2; mt++) {
                int rb = wm * 32 + mt * 16 + gp;
                float a0 = As[st][rb][k8 + qi],     a1 = As[st][rb + 8][k8 + qi];
                float a2 = As[st][rb][k8 + qi + 4], a3 = As[st][rb + 8][k8 + qi + 4];
                if (BN) {
                    a0 = fmaxf(fmaf(a0, sc0, sh0), 0.f);
                    a1 = fmaxf(fmaf(a1, sc0, sh0), 0.f);
                    a2 = fmaxf(fmaf(a2, sc4, sh4), 0.f);
                    a3 = fmaxf(fmaf(a3, sc4, sh4), 0.f);
                }
                a[mt][0] = __float_as_uint(to_tf32(a0));
                a[mt][1] = __float_as_uint(to_tf32(a1));
                a[mt][2] = __float_as_uint(to_tf32(a2));
                a[mt][3] = __float_as_uint(to_tf32(a3));
            }
#pragma unroll
            for (int nt = 0; nt < 8; nt++) {
                int cb = wn * 64 + nt * 8 + gp;
                b[nt][0] = __float_as_uint(to_tf32(Bs[st][k8 + qi][cb]));
                b[nt][1] = __float_as_uint(to_tf32(Bs[st][k8 + qi + 4][cb]));
            }
#pragma unroll
            for (int mt = 0; mt < 2; mt++)
#pragma unroll
                for (int nt = 0; nt < 8; nt++) {
                    asm volatile(
                        "mma.sync.aligned.m16n8k8.row.col.f32.tf32.tf32.f32 "
                        "{%0,%1,%2,%3},{%4,%5,%6,%7},{%8,%9},{%0,%1,%2,%3};"
                        : "+f"(acc[mt][nt][0]), "+f"(acc[mt][nt][1]),
                          "+f"(acc[mt][nt][2]), "+f"(acc[mt][nt][3])
                        : "r"(a[mt][0]), "r"(a[mt][1]), "r"(a[mt][2]), "r"(a[mt][3]),
                          "r"(b[nt][0]), "r"(b[nt][1]));
                }
        }
    };

    stage(0, 0);
    stage(1, 16);
#pragma unroll
    for (int i = 0; i < 8; i++) {
        if (i < 7) asm volatile("cp.async.wait_group 1;");
        else       asm volatile("cp.async.wait_group 0;");
        __syncthreads();
        compute(i & 1, i * 16);
        __syncthreads();
        if (i + 2 < 8) stage(i & 1, (i + 2) * 16);
    }

    // epilogue: fp16 store (+ optional att dots from fp32 accumulators)
#pragma unroll
    for (int mt = 0; mt < 2; mt++) {
#pragma unroll
        for (int h = 0; h < 2; h++) {
            int row = row0 + wm * 32 + mt * 16 + h * 8 + gp;
            bool ok = (row < NN);
            float ps = 0.f, pd = 0.f;
#pragma unroll
            for (int nt = 0; nt < 8; nt++) {
                int col = wn * 64 + nt * 8 + 2 * qi;
                float c0 = acc[mt][nt][2 * h], c1 = acc[mt][nt][2 * h + 1];
                if (ok) g_tmp[row * (HH / 2) + (col >> 1)] = __floats2half2_rn(c0, c1);
                if (ATT) {
                    ps = fmaf(c0, s_as[col], fmaf(c1, s_as[col + 1], ps));
                    pd = fmaf(c0, s_ad[col], fmaf(c1, s_ad[col + 1], pd));
                }
            }
            if (ATT) {
                ps += __shfl_xor_sync(0xffffffffu, ps, 1);
                ps += __shfl_xor_sync(0xffffffffu, ps, 2);
                pd += __shfl_xor_sync(0xffffffffu, pd, 1);
                pd += __shfl_xor_sync(0xffffffffu, pd, 2);
                if (qi == 0 && ok) {
                    atomicAdd(&g_als[row], ps);
                    atomicAdd(&g_ald[row], pd);
                }
            }
        }
    }
}

// ---------------- shared stats accumulation ----------------
__device__ __forceinline__ void stats_stripe(
    float4 acc, int w, int l, float (*ss)[128], float (*sq)[128]) {
    *(float4*)&ss[w][l * 4] = acc;
    *(float4*)&sq[w][l * 4] = make_float4(acc.x * acc.x, acc.y * acc.y,
                                          acc.z * acc.z, acc.w * acc.w);
    __syncthreads();
    int t = threadIdx.x;
    if (t < 128) {
        float S = 0.f, Q = 0.f;
#pragma unroll
        for (int ww = 0; ww < 8; ww++) { S += ss[ww][t]; Q += sq[ww][t]; }
        int stripe = (blockIdx.x & (NSTRIPE - 1)) * 128 + t;
        atomicAdd(&g_pS[stripe], S);
        atomicAdd(&g_pQ[stripe], Q);
    }
}

// ---------------- GCN segment aggregation ----------------
template<bool ZATT>
__global__ void k_gcn_seg(const float* __restrict__ bias) {
    __shared__ float ss[8][128], sq[8][128];
    int w = threadIdx.x >> 5, l = threadIdx.x & 31;
    int d = blockIdx.x * 8 + w;            // NN = 50000 = 6250*8
    float dd = g_dis[d];
    float4 b4 = ((const float4*)bias)[l];
    float4 self = load_row4(d, l);
    float dd2 = dd * dd;
    float4 acc = make_float4(fmaf(self.x, dd2, b4.x), fmaf(self.y, dd2, b4.y),
                             fmaf(self.z, dd2, b4.z), fmaf(self.w, dd2, b4.w));
    int deg = min(g_deg[d], BCAP);
    const int* bkt = &g_bkt[d * BCAP];
#pragma unroll 4
    for (int j = 0; j < deg; j++) {
        int s = __ldg(&bkt[j]);
        float nrm = g_dis[s] * dd;
        float4 v = load_row4(s, l);
        acc.x = fmaf(v.x, nrm, acc.x); acc.y = fmaf(v.y, nrm, acc.y);
        acc.z = fmaf(v.z, nrm, acc.z); acc.w = fmaf(v.w, nrm, acc.w);
    }
    ((float4*)&g_acc[d * HH])[l] = acc;
    if (ZATT && l == 0) { g_als[d] = 0.f; g_ald[d] = 0.f; }
    stats_stripe(acc, w, l, ss, sq);
}

// ---------------- GAT softmax + aggregation ----------------
__global__ void k_gat_seg(const float* __restrict__ bias) {
    __shared__ float ss[8][128], sq[8][128];
    int w = threadIdx.x >> 5, l = threadIdx.x & 31;
    int d = blockIdx.x * 8 + w;
    float ald_d = g_ald[d];
    float self_e = lrelu(g_als[d] + ald_d);
    int deg = min(g_deg[d], BCAP);
    const int* bkt = &g_bkt[d * BCAP];
    float m = self_e;
    for (int j = l; j < deg; j += 32)
        m = fmaxf(m, lrelu(g_als[__ldg(&bkt[j])] + ald_d));
#pragma unroll
    for (int o = 16; o; o >>= 1) m = fmaxf(m, __shfl_xor_sync(0xffffffffu, m, o));
    float den = 0.f;
    for (int j = l; j < deg; j += 32)
        den += expf(lrelu(g_als[__ldg(&bkt[j])] + ald_d) - m);
#pragma unroll
    for (int o = 16; o; o >>= 1) den += __shfl_xor_sync(0xffffffffu, den, o);
    den += expf(self_e - m);
    float rden = 1.0f / den;
    float4 b4 = ((const float4*)bias)[l];
    float a_self = expf(self_e - m) * rden;
    float4 self = load_row4(d, l);
    float4 acc = make_float4(fmaf(self.x, a_self, b4.x), fmaf(self.y, a_self, b4.y),
                             fmaf(self.z, a_self, b4.z), fmaf(self.w, a_self, b4.w));
#pragma unroll 2
    for (int j = 0; j < deg; j++) {
        int s = __ldg(&bkt[j]);
        float al = expf(lrelu(g_als[s] + ald_d) - m) * rden;
        float4 v = load_row4(s, l);
        acc.x = fmaf(v.x, al, acc.x); acc.y = fmaf(v.y, al, acc.y);
        acc.z = fmaf(v.z, al, acc.z); acc.w = fmaf(v.w, al, acc.w);
    }
    ((float4*)&g_acc[d * HH])[l] = acc;
    stats_stripe(acc, w, l, ss, sq);
}

// ---------------- BN finalize (1 block; reads stripes, re-zeros them) ------
__global__ void k_bn_prep(const float* __restrict__ gamma, const float* __restrict__ beta) {
    int c = threadIdx.x;               // 128 threads
    double S = 0.0, Q = 0.0;
    for (int s = 0; s < NSTRIPE; s++) {
        S += (double)g_pS[s * 128 + c];
        Q += (double)g_pQ[s * 128 + c];
        g_pS[s * 128 + c] = 0.f;
        g_pQ[s * 128 + c] = 0.f;
    }
    double mu = S / (double)NN;
    double var = Q / (double)NN - mu * mu;
    float vf = (float)var; if (vf < 0.f) vf = 0.f;
    float sc = gamma[c] * rsqrtf(vf + EPSF);
    g_scale[c] = sc;
    g_shift[c] = beta[c] - (float)mu * sc;
}

// ---------------- pooling (BN3+ReLU fused) + MLP ----------------
__global__ void k_pool_scatter(const int* __restrict__ batch) {
    int w = (blockIdx.x * blockDim.x + threadIdx.x) >> 5;
    if (w >= NN) return;
    int l = threadIdx.x & 31;
    int b = batch[w];
    if (!l) atomicAdd(&g_cnt[b], 1.0f);
    float4 v = ((const float4*)&g_acc[w * HH])[l];
    float4 sc = ((const float4*)g_scale)[l];
    float4 sh = ((const float4*)g_shift)[l];
    v.x = fmaxf(fmaf(v.x, sc.x, sh.x), 0.f);
    v.y = fmaxf(fmaf(v.y, sc.y, sh.y), 0.f);
    v.z = fmaxf(fmaf(v.z, sc.z, sh.z), 0.f);
    v.w = fmaxf(fmaf(v.w, sc.w, sh.w), 0.f);
    red_add_f4(&g_pooled[b * HH + l * 4], v);
}
__global__ void k_mlp(const float* __restrict__ fw1, const float* __restrict__ fb1,
                      const float* __restrict__ fw2, const float* __restrict__ fb2,
                      float* __restrict__ out) {
    __shared__ float p[HH], z[HH], r[4];
    int g = blockIdx.x, t = threadIdx.x;
    float inv = 1.0f / fmaxf(g_cnt[g], 1.0f);
    p[t] = g_pooled[g * HH + t] * inv;
    __syncthreads();
    float s = fb1[t];
#pragma unroll 8
    for (int k = 0; k < HH; k++) s = fmaf(p[k], fw1[k * HH + t], s);
    z[t] = fmaxf(s, 0.f);
    __syncthreads();
    float v = z[t] * fw2[t];
#pragma unroll
    for (int o = 16; o; o >>= 1) v += __shfl_xor_sync(0xffffffffu, v, o);
    if ((t & 31) == 0) r[t >> 5] = v;
    __syncthreads();
    if (t == 0) out[g] = r[0] + r[1] + r[2] + r[3] + fb2[0];
}

// ---------------- launch ----------------
extern "C" void kernel_launch(void* const* d_in, const int* in_sizes, int n_in,
                              void* d_out, int out_size) {
    const float* x       = (const float*)d_in[0];
    const int*   ei      = (const int*)d_in[1];
    const int*   batch   = (const int*)d_in[2];
    const float* W1      = (const float*)d_in[3];
    const float* b1      = (const float*)d_in[4];
    const float* g1      = (const float*)d_in[5];
    const float* be1     = (const float*)d_in[6];
    const float* Wg      = (const float*)d_in[7];
    const float* att_src = (const float*)d_in[8];
    const float* att_dst = (const float*)d_in[9];
    const float* bg      = (const float*)d_in[10];
    const float* g2      = (const float*)d_in[11];
    const float* be2     = (const float*)d_in[12];
    const float* W3      = (const float*)d_in[13];
    const float* b3      = (const float*)d_in[14];
    const float* g3      = (const float*)d_in[15];
    const float* be3     = (const float*)d_in[16];
    const float* fw1     = (const float*)d_in[17];
    const float* fb1     = (const float*)d_in[18];
    const float* fw2     = (const float*)d_in[19];
    const float* fb2     = (const float*)d_in[20];
    float* out = (float*)d_out;

    const int* src = ei;
    const int* dst = ei + EE;

    const int NB   = (NN + 255) / 256;
    const int EB   = (EE + 255) / 256;
    const int NWB  = (NN * 32 + 255) / 256;
    const int SEGB = NN / 8;                  // 6250 (exact)
    const int GEMB = (NN + 127) / 128;        // 391

    // graph structure
    k_zero<<<NB, 256>>>();
    k_fill<<<EB, 256>>>(src, dst);
    k_dis<<<NB, 256>>>();

    // ---- layer 1: GCN ----
    k_gemm<false, false><<<GEMB, 256>>>(x, W1, nullptr, nullptr);
    k_gcn_seg<true><<<SEGB, 256>>>(b1);               // + zero att accumulators
    k_bn_prep<<<1, 128>>>(g1, be1);

    // ---- layer 2: GAT (BN1 fused into GEMM; att dots in epilogue) ----
    k_gemm<true, true><<<GEMB, 256>>>(nullptr, Wg, att_src, att_dst);
    k_gat_seg<<<SEGB, 256>>>(bg);
    k_bn_prep<<<1, 128>>>(g2, be2);

    // ---- layer 3: GCN (BN2 fused into GEMM) ----
    k_gemm<true, false><<<GEMB, 256>>>(nullptr, W3, nullptr, nullptr);
    k_gcn_seg<false><<<SEGB, 256>>>(b3);
    k_bn_prep<<<1, 128>>>(g3, be3);

    // ---- pool (BN3+ReLU fused) + MLP ----
    k_pool_scatter<<<NWB, 256>>>(batch);
    k_mlp<<<GG, 128>>>(fw1, fb1, fw2, fb2, out);
}

// round 8
// speedup vs baseline: 1.2494x; 1.1206x over previous
#include <cuda_runtime.h>
#include <cuda_fp16.h>
#include <math.h>
#include <stdint.h>

// ---------------- problem constants ----------------
#define NN 50000
#define EE 600000
#define HH 128
#define GG 256
#define EPSF 1e-5f
#define SLOPE 0.2f
#define NSTRIPE 64
#define BCAP 64            // bucket capacity per node (Poisson(12) => P(>64) ~ 0)

// ---------------- scratch ----------------
__device__ __align__(16) __half2 g_tmp[NN * (HH / 2)];  // GEMM output, fp16 payload
__device__ __align__(16) float g_acc[NN * HH];          // aggregated pre-BN activations
__device__ float g_dis[NN];
__device__ float g_als[NN], g_ald[NN];
__device__ int   g_deg[NN];
__device__ int   g_bkt[NN * BCAP];               // direct-bucket CSR
__device__ float g_pS[NSTRIPE * HH], g_pQ[NSTRIPE * HH];
__device__ __align__(16) float g_scale[HH], g_shift[HH];
__device__ __align__(16) float g_pooled[GG * HH];
__device__ float g_cnt[GG];

__device__ __forceinline__ float lrelu(float x) { return x > 0.f ? x : SLOPE * x; }

__device__ __forceinline__ float to_tf32(float x) {
    float r;
    asm("cvt.rna.tf32.f32 %0, %1;" : "=f"(r) : "f"(x));
    return r;
}

__device__ __forceinline__ void red_add_f4(float* p, float4 v) {
    asm volatile("red.global.add.v4.f32 [%0], {%1,%2,%3,%4};"
                 :: "l"(__cvta_generic_to_global(p)),
                    "f"(v.x), "f"(v.y), "f"(v.z), "f"(v.w)
                 : "memory");
}

// gather 4 floats (cols 4l..4l+3) of node s from fp16 payload
__device__ __forceinline__ float4 load_row4(int s, int l) {
    uint2 u = *(const uint2*)&g_tmp[s * (HH / 2) + l * 2];
    float2 f0 = __half22float2(*(__half2*)&u.x);
    float2 f1 = __half22float2(*(__half2*)&u.y);
    return make_float4(f0.x, f0.y, f1.x, f1.y);
}

__device__ __forceinline__ void acc4(float4& a, float4 v, float wt) {
    a.x = fmaf(v.x, wt, a.x); a.y = fmaf(v.y, wt, a.y);
    a.z = fmaf(v.z, wt, a.z); a.w = fmaf(v.w, wt, a.w);
}

// ---------------- zero + bucket CSR build ----------------
__global__ void k_zero() {
    int i = blockIdx.x * blockDim.x + threadIdx.x;
    if (i < NN) g_deg[i] = 0;
    if (i < GG) g_cnt[i] = 0.f;
    if (i < GG * HH) g_pooled[i] = 0.f;
    if (i < NSTRIPE * HH) { g_pS[i] = 0.f; g_pQ[i] = 0.f; }
}
__global__ void k_fill(const int* __restrict__ src, const int* __restrict__ dst) {
    int e0 = (blockIdx.x * blockDim.x + threadIdx.x) * 4;
    if (e0 >= EE) return;
    int4 s4 = *(const int4*)&src[e0];
    int4 d4 = *(const int4*)&dst[e0];
    int p0 = atomicAdd(&g_deg[d4.x], 1);
    int p1 = atomicAdd(&g_deg[d4.y], 1);
    int p2 = atomicAdd(&g_deg[d4.z], 1);
    int p3 = atomicAdd(&g_deg[d4.w], 1);
    if (p0 < BCAP) g_bkt[d4.x * BCAP + p0] = s4.x;
    if (p1 < BCAP) g_bkt[d4.y * BCAP + p1] = s4.y;
    if (p2 < BCAP) g_bkt[d4.z * BCAP + p2] = s4.z;
    if (p3 < BCAP) g_bkt[d4.w * BCAP + p3] = s4.w;
}
__global__ void k_dis() {
    int i = blockIdx.x * blockDim.x + threadIdx.x;
    if (i < NN) g_dis[i] = rsqrtf(1.0f + (float)g_deg[i]);
}

// ---------------- TF32 tensor-core GEMM, cp.async 2-stage pipeline ----------
template<bool BN, bool ATT>
__global__ __launch_bounds__(256, 2)
void k_gemm(const float* __restrict__ Aext, const float* __restrict__ W,
            const float* __restrict__ av_s, const float* __restrict__ av_d) {
    __shared__ float As[2][128][20];     // [stage][row][k] raw fp32, k-chunk=16
    __shared__ float Bs[2][16][136];     // [stage][k][n]   raw fp32
    __shared__ float s_sc[128], s_sh[128], s_as[128], s_ad[128];
    const float* A = BN ? (const float*)g_acc : Aext;
    int t = threadIdx.x;
    if (t < 128) {
        if (BN)  { s_sc[t] = g_scale[t]; s_sh[t] = g_shift[t]; }
        if (ATT) { s_as[t] = av_s[t];    s_ad[t] = av_d[t]; }
    }
    int row0 = blockIdx.x * 128;
    int warpId = t >> 5, lane = t & 31;
    int wm = warpId >> 1, wn = warpId & 1;   // 4 x 2 warp grid
    int gp = lane >> 2, qi = lane & 3;

    int arow = t >> 2;            // 0..63 (two passes of 64 rows)
    int ac4  = (t & 3) * 4;       // 0,4,8,12
    int brow = t >> 5;            // 0..7  (two passes of 8 rows)
    int bc4  = (t & 31) * 4;

    float acc[2][8][4];
#pragma unroll
    for (int mt = 0; mt < 2; mt++)
#pragma unroll
        for (int nt = 0; nt < 8; nt++)
#pragma unroll
            for (int j = 0; j < 4; j++) acc[mt][nt][j] = 0.f;

    auto stage = [&](int st, int kt) {
#pragma unroll
        for (int p = 0; p < 2; p++) {
            int r = p * 64 + arow;
            int grow = row0 + r;
            uint32_t sa = (uint32_t)__cvta_generic_to_shared(&As[st][r][ac4]);
            const float* gp_ = &A[(size_t)grow * 128 + kt + ac4];
            int sz = (grow < NN) ? 16 : 0;
            asm volatile("cp.async.cg.shared.global [%0], [%1], 16, %2;"
                         :: "r"(sa), "l"(gp_), "r"(sz));
        }
#pragma unroll
        for (int p = 0; p < 2; p++) {
            int r = p * 8 + brow;
            uint32_t sa = (uint32_t)__cvta_generic_to_shared(&Bs[st][r][bc4]);
            const float* gp_ = &W[(kt + r) * 128 + bc4];
            asm volatile("cp.async.cg.shared.global [%0], [%1], 16, 16;"
                         :: "r"(sa), "l"(gp_));
        }
        asm volatile("cp.async.commit_group;");
    };

    auto compute = [&](int st, int kt) {
#pragma unroll
        for (int k8 = 0; k8 < 16; k8 += 8) {
            float sc0 = 0.f, sh0 = 0.f, sc4 = 0.f, sh4 = 0.f;
            if (BN) {
                sc0 = s_sc[kt + k8 + qi];     sh0 = s_sh[kt + k8 + qi];
                sc4 = s_sc[kt + k8 + qi + 4]; sh4 = s_sh[kt + k8 + qi + 4];
            }
            uint32_t a[2][4], b[8][2];
#pragma unroll
            for (int mt = 0; mt < 2; mt++) {
                int rb = wm * 32 + mt * 16 + gp;
                float a0 = As[st][rb][k8 + qi],     a1 = As[st][rb + 8][k8 + qi];
                float a2 = As[st][rb][k8 + qi + 4], a3 = As[st][rb + 8][k8 + qi + 4];
                if (BN) {
                    a0 = fmaxf(fmaf(a0, sc0, sh0), 0.f);
                    a1 = fmaxf(fmaf(a1, sc0, sh0), 0.f);
                    a2 = fmaxf(fmaf(a2, sc4, sh4), 0.f);
                    a3 = fmaxf(fmaf(a3, sc4, sh4), 0.f);
                }
                a[mt][0] = __float_as_uint(to_tf32(a0));
                a[mt][1] = __float_as_uint(to_tf32(a1));
                a[mt][2] = __float_as_uint(to_tf32(a2));
                a[mt][3] = __float_as_uint(to_tf32(a3));
            }
#pragma unroll
            for (int nt = 0; nt < 8; nt++) {
                int cb = wn * 64 + nt * 8 + gp;
                b[nt][0] = __float_as_uint(to_tf32(Bs[st][k8 + qi][cb]));
                b[nt][1] = __float_as_uint(to_tf32(Bs[st][k8 + qi + 4][cb]));
            }
#pragma unroll
            for (int mt = 0; mt < 2; mt++)
#pragma unroll
                for (int nt = 0; nt < 8; nt++) {
                    asm volatile(
                        "mma.sync.aligned.m16n8k8.row.col.f32.tf32.tf32.f32 "
                        "{%0,%1,%2,%3},{%4,%5,%6,%7},{%8,%9},{%0,%1,%2,%3};"
                        : "+f"(acc[mt][nt][0]), "+f"(acc[mt][nt][1]),
                          "+f"(acc[mt][nt][2]), "+f"(acc[mt][nt][3])
                        : "r"(a[mt][0]), "r"(a[mt][1]), "r"(a[mt][2]), "r"(a[mt][3]),
                          "r"(b[nt][0]), "r"(b[nt][1]));
                }
        }
    };

    stage(0, 0);
    stage(1, 16);
#pragma unroll
    for (int i = 0; i < 8; i++) {
        if (i < 7) asm volatile("cp.async.wait_group 1;");
        else       asm volatile("cp.async.wait_group 0;");
        __syncthreads();
        compute(i & 1, i * 16);
        __syncthreads();
        if (i + 2 < 8) stage(i & 1, (i + 2) * 16);
    }

    // epilogue: fp16 store (+ optional att dots from fp32 accumulators)
#pragma unroll
    for (int mt = 0; mt < 2; mt++) {
#pragma unroll
        for (int h = 0; h < 2; h++) {
            int row = row0 + wm * 32 + mt * 16 + h * 8 + gp;
            bool ok = (row < NN);
            float ps = 0.f, pd = 0.f;
#pragma unroll
            for (int nt = 0; nt < 8; nt++) {
                int col = wn * 64 + nt * 8 + 2 * qi;
                float c0 = acc[mt][nt][2 * h], c1 = acc[mt][nt][2 * h + 1];
                if (ok) g_tmp[row * (HH / 2) + (col >> 1)] = __floats2half2_rn(c0, c1);
                if (ATT) {
                    ps = fmaf(c0, s_as[col], fmaf(c1, s_as[col + 1], ps));
                    pd = fmaf(c0, s_ad[col], fmaf(c1, s_ad[col + 1], pd));
                }
            }
            if (ATT) {
                ps += __shfl_xor_sync(0xffffffffu, ps, 1);
                ps += __shfl_xor_sync(0xffffffffu, ps, 2);
                pd += __shfl_xor_sync(0xffffffffu, pd, 1);
                pd += __shfl_xor_sync(0xffffffffu, pd, 2);
                if (qi == 0 && ok) {
                    atomicAdd(&g_als[row], ps);
                    atomicAdd(&g_ald[row], pd);
                }
            }
        }
    }
}

// ---------------- shared stats accumulation ----------------
__device__ __forceinline__ void stats_stripe(
    float4 a, int w, int l, float (*ss)[128], float (*sq)[128]) {
    *(float4*)&ss[w][l * 4] = a;
    *(float4*)&sq[w][l * 4] = make_float4(a.x * a.x, a.y * a.y, a.z * a.z, a.w * a.w);
    __syncthreads();
    int t = threadIdx.x;
    if (t < 128) {
        float S = 0.f, Q = 0.f;
#pragma unroll
        for (int ww = 0; ww < 8; ww++) { S += ss[ww][t]; Q += sq[ww][t]; }
        int stripe = (blockIdx.x & (NSTRIPE - 1)) * 128 + t;
        atomicAdd(&g_pS[stripe], S);
        atomicAdd(&g_pQ[stripe], Q);
    }
}

// ---------------- GCN segment aggregation (batched gather pipeline) --------
template<bool ZATT>
__global__ void k_gcn_seg(const float* __restrict__ bias) {
    __shared__ float ss[8][128], sq[8][128];
    int w = threadIdx.x >> 5, l = threadIdx.x & 31;
    int d = blockIdx.x * 8 + w;            // NN = 50000 = 6250*8
    float dd = g_dis[d];
    float4 b4 = ((const float4*)bias)[l];
    float4 self = load_row4(d, l);
    float dd2 = dd * dd;
    float4 acc = make_float4(fmaf(self.x, dd2, b4.x), fmaf(self.y, dd2, b4.y),
                             fmaf(self.z, dd2, b4.z), fmaf(self.w, dd2, b4.w));
    int deg = min(g_deg[d], BCAP);
    const int* bkt = &g_bkt[d * BCAP];
    int j = 0;
    for (; j + 8 <= deg; j += 8) {
        int sidx[8];
#pragma unroll
        for (int u = 0; u < 8; u++) sidx[u] = __ldg(&bkt[j + u]);
        float nrm[8]; float4 v[8];
#pragma unroll
        for (int u = 0; u < 8; u++) { nrm[u] = g_dis[sidx[u]] * dd; v[u] = load_row4(sidx[u], l); }
#pragma unroll
        for (int u = 0; u < 8; u++) acc4(acc, v[u], nrm[u]);
    }
    if (j + 4 <= deg) {
        int sidx[4];
#pragma unroll
        for (int u = 0; u < 4; u++) sidx[u] = __ldg(&bkt[j + u]);
        float nrm[4]; float4 v[4];
#pragma unroll
        for (int u = 0; u < 4; u++) { nrm[u] = g_dis[sidx[u]] * dd; v[u] = load_row4(sidx[u], l); }
#pragma unroll
        for (int u = 0; u < 4; u++) acc4(acc, v[u], nrm[u]);
        j += 4;
    }
    for (; j < deg; j++) {
        int s = __ldg(&bkt[j]);
        float nrm = g_dis[s] * dd;
        acc4(acc, load_row4(s, l), nrm);
    }
    ((float4*)&g_acc[d * HH])[l] = acc;
    if (ZATT && l == 0) { g_als[d] = 0.f; g_ald[d] = 0.f; }
    stats_stripe(acc, w, l, ss, sq);
}

// ---------------- GAT softmax + aggregation (single-pass, smem staged) -----
__global__ void k_gat_seg(const float* __restrict__ bias) {
    __shared__ float ss[8][128], sq[8][128];
    __shared__ float s_ex[8][BCAP];
    __shared__ int   s_idx[8][BCAP];
    int w = threadIdx.x >> 5, l = threadIdx.x & 31;
    int d = blockIdx.x * 8 + w;
    float ald_d = g_ald[d];
    float self_e = lrelu(g_als[d] + ald_d);
    int deg = min(g_deg[d], BCAP);
    const int* bkt = &g_bkt[d * BCAP];

    // lane-strided: each lane owns up to 2 neighbors
    int i0 = l, i1 = l + 32;
    int n0 = (i0 < deg) ? __ldg(&bkt[i0]) : 0;
    int n1 = (i1 < deg) ? __ldg(&bkt[i1]) : 0;
    float e0 = (i0 < deg) ? lrelu(g_als[n0] + ald_d) : -1e30f;
    float e1 = (i1 < deg) ? lrelu(g_als[n1] + ald_d) : -1e30f;
    float m = fmaxf(self_e, fmaxf(e0, e1));
#pragma unroll
    for (int o = 16; o; o >>= 1) m = fmaxf(m, __shfl_xor_sync(0xffffffffu, m, o));
    float ex0 = (i0 < deg) ? expf(e0 - m) : 0.f;
    float ex1 = (i1 < deg) ? expf(e1 - m) : 0.f;
    float den = ex0 + ex1;
#pragma unroll
    for (int o = 16; o; o >>= 1) den += __shfl_xor_sync(0xffffffffu, den, o);
    den += expf(self_e - m);
    float rden = 1.0f / den;
    if (i0 < deg) { s_ex[w][i0] = ex0; s_idx[w][i0] = n0; }
    if (i1 < deg) { s_ex[w][i1] = ex1; s_idx[w][i1] = n1; }
    __syncwarp();

    float4 b4 = ((const float4*)bias)[l];
    float a_self = expf(self_e - m) * rden;
    float4 self = load_row4(d, l);
    float4 acc = make_float4(fmaf(self.x, a_self, b4.x), fmaf(self.y, a_self, b4.y),
                             fmaf(self.z, a_self, b4.z), fmaf(self.w, a_self, b4.w));
    int j = 0;
    for (; j + 8 <= deg; j += 8) {
        int sidx[8]; float al[8];
#pragma unroll
        for (int u = 0; u < 8; u++) { sidx[u] = s_idx[w][j + u]; al[u] = s_ex[w][j + u] * rden; }
        float4 v[8];
#pragma unroll
        for (int u = 0; u < 8; u++) v[u] = load_row4(sidx[u], l);
#pragma unroll
        for (int u = 0; u < 8; u++) acc4(acc, v[u], al[u]);
    }
    if (j + 4 <= deg) {
        int sidx[4]; float al[4];
#pragma unroll
        for (int u = 0; u < 4; u++) { sidx[u] = s_idx[w][j + u]; al[u] = s_ex[w][j + u] * rden; }
        float4 v[4];
#pragma unroll
        for (int u = 0; u < 4; u++) v[u] = load_row4(sidx[u], l);
#pragma unroll
        for (int u = 0; u < 4; u++) acc4(acc, v[u], al[u]);
        j += 4;
    }
    for (; j < deg; j++) {
        float al = s_ex[w][j] * rden;
        acc4(acc, load_row4(s_idx[w][j], l), al);
    }
    ((float4*)&g_acc[d * HH])[l] = acc;
    stats_stripe(acc, w, l, ss, sq);
}

// ---------------- BN finalize (1 block; reads stripes, re-zeros them) ------
__global__ void k_bn_prep(const float* __restrict__ gamma, const float* __restrict__ beta) {
    int c = threadIdx.x;               // 128 threads
    double S = 0.0, Q = 0.0;
    for (int s = 0; s < NSTRIPE; s++) {
        S += (double)g_pS[s * 128 + c];
        Q += (double)g_pQ[s * 128 + c];
        g_pS[s * 128 + c] = 0.f;
        g_pQ[s * 128 + c] = 0.f;
    }
    double mu = S / (double)NN;
    double var = Q / (double)NN - mu * mu;
    float vf = (float)var; if (vf < 0.f) vf = 0.f;
    float sc = gamma[c] * rsqrtf(vf + EPSF);
    g_scale[c] = sc;
    g_shift[c] = beta[c] - (float)mu * sc;
}

// ---------------- pooling (BN3+ReLU fused) + MLP ----------------
__global__ void k_pool_scatter(const int* __restrict__ batch) {
    int w = (blockIdx.x * blockDim.x + threadIdx.x) >> 5;
    if (w >= NN) return;
    int l = threadIdx.x & 31;
    int b = batch[w];
    if (!l) atomicAdd(&g_cnt[b], 1.0f);
    float4 v = ((const float4*)&g_acc[w * HH])[l];
    float4 sc = ((const float4*)g_scale)[l];
    float4 sh = ((const float4*)g_shift)[l];
    v.x = fmaxf(fmaf(v.x, sc.x, sh.x), 0.f);
    v.y = fmaxf(fmaf(v.y, sc.y, sh.y), 0.f);
    v.z = fmaxf(fmaf(v.z, sc.z, sh.z), 0.f);
    v.w = fmaxf(fmaf(v.w, sc.w, sh.w), 0.f);
    red_add_f4(&g_pooled[b * HH + l * 4], v);
}
__global__ void k_mlp(const float* __restrict__ fw1, const float* __restrict__ fb1,
                      const float* __restrict__ fw2, const float* __restrict__ fb2,
                      float* __restrict__ out) {
    __shared__ float p[HH], z[HH], r[4];
    int g = blockIdx.x, t = threadIdx.x;
    float inv = 1.0f / fmaxf(g_cnt[g], 1.0f);
    p[t] = g_pooled[g * HH + t] * inv;
    __syncthreads();
    float s = fb1[t];
#pragma unroll 8
    for (int k = 0; k < HH; k++) s = fmaf(p[k], fw1[k * HH + t], s);
    z[t] = fmaxf(s, 0.f);
    __syncthreads();
    float v = z[t] * fw2[t];
#pragma unroll
    for (int o = 16; o; o >>= 1) v += __shfl_xor_sync(0xffffffffu, v, o);
    if ((t & 31) == 0) r[t >> 5] = v;
    __syncthreads();
    if (t == 0) out[g] = r[0] + r[1] + r[2] + r[3] + fb2[0];
}

// ---------------- launch ----------------
extern "C" void kernel_launch(void* const* d_in, const int* in_sizes, int n_in,
                              void* d_out, int out_size) {
    const float* x       = (const float*)d_in[0];
    const int*   ei      = (const int*)d_in[1];
    const int*   batch   = (const int*)d_in[2];
    const float* W1      = (const float*)d_in[3];
    const float* b1      = (const float*)d_in[4];
    const float* g1      = (const float*)d_in[5];
    const float* be1     = (const float*)d_in[6];
    const float* Wg      = (const float*)d_in[7];
    const float* att_src = (const float*)d_in[8];
    const float* att_dst = (const float*)d_in[9];
    const float* bg      = (const float*)d_in[10];
    const float* g2      = (const float*)d_in[11];
    const float* be2     = (const float*)d_in[12];
    const float* W3      = (const float*)d_in[13];
    const float* b3      = (const float*)d_in[14];
    const float* g3      = (const float*)d_in[15];
    const float* be3     = (const float*)d_in[16];
    const float* fw1     = (const float*)d_in[17];
    const float* fb1     = (const float*)d_in[18];
    const float* fw2     = (const float*)d_in[19];
    const float* fb2     = (const float*)d_in[20];
    float* out = (float*)d_out;

    const int* src = ei;
    const int* dst = ei + EE;

    const int NB   = (NN + 255) / 256;
    const int EB4  = (EE / 4 + 255) / 256;
    const int NWB  = (NN * 32 + 255) / 256;
    const int SEGB = NN / 8;                  // 6250 (exact)
    const int GEMB = (NN + 127) / 128;        // 391

    // graph structure
    k_zero<<<NB, 256>>>();
    k_fill<<<EB4, 256>>>(src, dst);
    k_dis<<<NB, 256>>>();

    // ---- layer 1: GCN ----
    k_gemm<false, false><<<GEMB, 256>>>(x, W1, nullptr, nullptr);
    k_gcn_seg<true><<<SEGB, 256>>>(b1);               // + zero att accumulators
    k_bn_prep<<<1, 128>>>(g1, be1);

    // ---- layer 2: GAT (BN1 fused into GEMM; att dots in epilogue) ----
    k_gemm<true, true><<<GEMB, 256>>>(nullptr, Wg, att_src, att_dst);
    k_gat_seg<<<SEGB, 256>>>(bg);
    k_bn_prep<<<1, 128>>>(g2, be2);

    // ---- layer 3: GCN (BN2 fused into GEMM) ----
    k_gemm<true, false><<<GEMB, 256>>>(nullptr, W3, nullptr, nullptr);
    k_gcn_seg<false><<<SEGB, 256>>>(b3);
    k_bn_prep<<<1, 128>>>(g3, be3);

    // ---- pool (BN3+ReLU fused) + MLP ----
    k_pool_scatter<<<NWB, 256>>>(batch);
    k_mlp<<<GG, 128>>>(fw1, fb1, fw2, fb2, out);
}

// round 9
// speedup vs baseline: 1.3896x; 1.1122x over previous
#include <cuda_runtime.h>
#include <cuda_fp16.h>
#include <math.h>
#include <stdint.h>

// ---------------- problem constants ----------------
#define NN 50000
#define EE 600000
#define HH 128
#define GG 256
#define EPSF 1e-5f
#define SLOPE 0.2f
#define NSTRIPE 64
#define BCAP 64            // bucket capacity per node (Poisson(12) => P(>64) ~ 0)

// ---------------- scratch ----------------
__device__ __align__(16) __half2 g_tmp[NN * (HH / 2)];  // GEMM output, fp16 payload
__device__ __align__(16) float g_acc[NN * HH];          // aggregated pre-BN activations
__device__ float g_als[NN], g_ald[NN];
__device__ int   g_deg[NN];
__device__ int   g_bkt[NN * BCAP];               // direct-bucket CSR
__device__ int   g_gptr[GG + 1];                 // graph row ranges (batch is sorted)
__device__ float g_pS[NSTRIPE * HH], g_pQ[NSTRIPE * HH];
__device__ __align__(16) float g_scale[HH], g_shift[HH];

__device__ __forceinline__ float lrelu(float x) { return x > 0.f ? x : SLOPE * x; }

__device__ __forceinline__ float to_tf32(float x) {
    float r;
    asm("cvt.rna.tf32.f32 %0, %1;" : "=f"(r) : "f"(x));
    return r;
}

// gather 4 floats (cols 4l..4l+3) of node s from fp16 payload
__device__ __forceinline__ float4 load_row4(int s, int l) {
    uint2 u = *(const uint2*)&g_tmp[s * (HH / 2) + l * 2];
    float2 f0 = __half22float2(*(__half2*)&u.x);
    float2 f1 = __half22float2(*(__half2*)&u.y);
    return make_float4(f0.x, f0.y, f1.x, f1.y);
}

__device__ __forceinline__ void acc4(float4& a, float4 v, float wt) {
    a.x = fmaf(v.x, wt, a.x); a.y = fmaf(v.y, wt, a.y);
    a.z = fmaf(v.z, wt, a.z); a.w = fmaf(v.w, wt, a.w);
}

// ---------------- zero + graph boundaries (batch is sorted) ----------------
__global__ void k_zero(const int* __restrict__ batch) {
    int i = blockIdx.x * blockDim.x + threadIdx.x;
    if (i < NN) {
        g_deg[i] = 0;
        int b = batch[i];
        if (i == 0) {
            for (int g = 0; g <= b; g++) g_gptr[g] = 0;
        } else {
            int pb = batch[i - 1];
            for (int g = pb + 1; g <= b; g++) g_gptr[g] = i;
        }
        if (i == NN - 1) {
            for (int g = b + 1; g <= GG; g++) g_gptr[g] = NN;
        }
    }
    if (i < NSTRIPE * HH) { g_pS[i] = 0.f; g_pQ[i] = 0.f; }
}
__global__ void k_fill(const int* __restrict__ src, const int* __restrict__ dst) {
    int e0 = (blockIdx.x * blockDim.x + threadIdx.x) * 4;
    if (e0 >= EE) return;
    int4 s4 = *(const int4*)&src[e0];
    int4 d4 = *(const int4*)&dst[e0];
    int p0 = atomicAdd(&g_deg[d4.x], 1);
    int p1 = atomicAdd(&g_deg[d4.y], 1);
    int p2 = atomicAdd(&g_deg[d4.z], 1);
    int p3 = atomicAdd(&g_deg[d4.w], 1);
    if (p0 < BCAP) g_bkt[d4.x * BCAP + p0] = s4.x;
    if (p1 < BCAP) g_bkt[d4.y * BCAP + p1] = s4.y;
    if (p2 < BCAP) g_bkt[d4.z * BCAP + p2] = s4.z;
    if (p3 < BCAP) g_bkt[d4.w * BCAP + p3] = s4.w;
}

// ---------------- TF32 tensor-core GEMM, cp.async 2-stage pipeline ----------
template<bool BN, bool ATT>
__global__ __launch_bounds__(256, 2)
void k_gemm(const float* __restrict__ Aext, const float* __restrict__ W,
            const float* __restrict__ av_s, const float* __restrict__ av_d) {
    __shared__ float As[2][128][20];     // [stage][row][k] raw fp32, k-chunk=16
    __shared__ float Bs[2][16][136];     // [stage][k][n]   raw fp32
    __shared__ float s_sc[128], s_sh[128], s_as[128], s_ad[128];
    const float* A = BN ? (const float*)g_acc : Aext;
    int t = threadIdx.x;
    if (t < 128) {
        if (BN)  { s_sc[t] = g_scale[t]; s_sh[t] = g_shift[t]; }
        if (ATT) { s_as[t] = av_s[t];    s_ad[t] = av_d[t]; }
    }
    int row0 = blockIdx.x * 128;
    int warpId = t >> 5, lane = t & 31;
    int wm = warpId >> 1, wn = warpId & 1;   // 4 x 2 warp grid
    int gp = lane >> 2, qi = lane & 3;

    int arow = t >> 2;            // 0..63 (two passes of 64 rows)
    int ac4  = (t & 3) * 4;       // 0,4,8,12
    int brow = t >> 5;            // 0..7  (two passes of 8 rows)
    int bc4  = (t & 31) * 4;

    float acc[2][8][4];
#pragma unroll
    for (int mt = 0; mt < 2; mt++)
#pragma unroll
        for (int nt = 0; nt < 8; nt++)
#pragma unroll
            for (int j = 0; j < 4; j++) acc[mt][nt][j] = 0.f;

    auto stage = [&](int st, int kt) {
#pragma unroll
        for (int p = 0; p < 2; p++) {
            int r = p * 64 + arow;
            int grow = row0 + r;
            uint32_t sa = (uint32_t)__cvta_generic_to_shared(&As[st][r][ac4]);
            const float* gp_ = &A[(size_t)grow * 128 + kt + ac4];
            int sz = (grow < NN) ? 16 : 0;
            asm volatile("cp.async.cg.shared.global [%0], [%1], 16, %2;"
                         :: "r"(sa), "l"(gp_), "r"(sz));
        }
#pragma unroll
        for (int p = 0; p < 2; p++) {
            int r = p * 8 + brow;
            uint32_t sa = (uint32_t)__cvta_generic_to_shared(&Bs[st][r][bc4]);
            const float* gp_ = &W[(kt + r) * 128 + bc4];
            asm volatile("cp.async.cg.shared.global [%0], [%1], 16, 16;"
                         :: "r"(sa), "l"(gp_));
        }
        asm volatile("cp.async.commit_group;");
    };

    auto compute = [&](int st, int kt) {
#pragma unroll
        for (int k8 = 0; k8 < 16; k8 += 8) {
            float sc0 = 0.f, sh0 = 0.f, sc4 = 0.f, sh4 = 0.f;
            if (BN) {
                sc0 = s_sc[kt + k8 + qi];     sh0 = s_sh[kt + k8 + qi];
                sc4 = s_sc[kt + k8 + qi + 4]; sh4 = s_sh[kt + k8 + qi + 4];
            }
            uint32_t a[2][4], b[8][2];
#pragma unroll
            for (int mt = 0; mt < 2; mt++) {
                int rb = wm * 32 + mt * 16 + gp;
                float a0 = As[st][rb][k8 + qi],     a1 = As[st][rb + 8][k8 + qi];
                float a2 = As[st][rb][k8 + qi + 4], a3 = As[st][rb + 8][k8 + qi + 4];
                if (BN) {
                    a0 = fmaxf(fmaf(a0, sc0, sh0), 0.f);
                    a1 = fmaxf(fmaf(a1, sc0, sh0), 0.f);
                    a2 = fmaxf(fmaf(a2, sc4, sh4), 0.f);
                    a3 = fmaxf(fmaf(a3, sc4, sh4), 0.f);
                }
                a[mt][0] = __float_as_uint(to_tf32(a0));
                a[mt][1] = __float_as_uint(to_tf32(a1));
                a[mt][2] = __float_as_uint(to_tf32(a2));
                a[mt][3] = __float_as_uint(to_tf32(a3));
            }
#pragma unroll
            for (int nt = 0; nt < 8; nt++) {
                int cb = wn * 64 + nt * 8 + gp;
                b[nt][0] = __float_as_uint(to_tf32(Bs[st][k8 + qi][cb]));
                b[nt][1] = __float_as_uint(to_tf32(Bs[st][k8 + qi + 4][cb]));
            }
#pragma unroll
            for (int mt = 0; mt < 2; mt++)
#pragma unroll
                for (int nt = 0; nt < 8; nt++) {
                    asm volatile(
                        "mma.sync.aligned.m16n8k8.row.col.f32.tf32.tf32.f32 "
                        "{%0,%1,%2,%3},{%4,%5,%6,%7},{%8,%9},{%0,%1,%2,%3};"
                        : "+f"(acc[mt][nt][0]), "+f"(acc[mt][nt][1]),
                          "+f"(acc[mt][nt][2]), "+f"(acc[mt][nt][3])
                        : "r"(a[mt][0]), "r"(a[mt][1]), "r"(a[mt][2]), "r"(a[mt][3]),
                          "r"(b[nt][0]), "r"(b[nt][1]));
                }
        }
    };

    stage(0, 0);
    stage(1, 16);
#pragma unroll
    for (int i = 0; i < 8; i++) {
        if (i < 7) asm volatile("cp.async.wait_group 1;");
        else       asm volatile("cp.async.wait_group 0;");
        __syncthreads();
        compute(i & 1, i * 16);
        __syncthreads();
        if (i + 2 < 8) stage(i & 1, (i + 2) * 16);
    }

    // epilogue: fp16 store (+ optional att dots from fp32 accumulators)
#pragma unroll
    for (int mt = 0; mt < 2; mt++) {
#pragma unroll
        for (int h = 0; h < 2; h++) {
            int row = row0 + wm * 32 + mt * 16 + h * 8 + gp;
            bool ok = (row < NN);
            float ps = 0.f, pd = 0.f;
#pragma unroll
            for (int nt = 0; nt < 8; nt++) {
                int col = wn * 64 + nt * 8 + 2 * qi;
                float c0 = acc[mt][nt][2 * h], c1 = acc[mt][nt][2 * h + 1];
                if (ok) g_tmp[row * (HH / 2) + (col >> 1)] = __floats2half2_rn(c0, c1);
                if (ATT) {
                    ps = fmaf(c0, s_as[col], fmaf(c1, s_as[col + 1], ps));
                    pd = fmaf(c0, s_ad[col], fmaf(c1, s_ad[col + 1], pd));
                }
            }
            if (ATT) {
                ps += __shfl_xor_sync(0xffffffffu, ps, 1);
                ps += __shfl_xor_sync(0xffffffffu, ps, 2);
                pd += __shfl_xor_sync(0xffffffffu, pd, 1);
                pd += __shfl_xor_sync(0xffffffffu, pd, 2);
                if (qi == 0 && ok) {
                    atomicAdd(&g_als[row], ps);
                    atomicAdd(&g_ald[row], pd);
                }
            }
        }
    }
}

// ---------------- shared stats accumulation ----------------
__device__ __forceinline__ void stats_stripe(
    float4 a, int w, int l, float (*ss)[128], float (*sq)[128]) {
    *(float4*)&ss[w][l * 4] = a;
    *(float4*)&sq[w][l * 4] = make_float4(a.x * a.x, a.y * a.y, a.z * a.z, a.w * a.w);
    __syncthreads();
    int t = threadIdx.x;
    if (t < 128) {
        float S = 0.f, Q = 0.f;
#pragma unroll
        for (int ww = 0; ww < 8; ww++) { S += ss[ww][t]; Q += sq[ww][t]; }
        int stripe = (blockIdx.x & (NSTRIPE - 1)) * 128 + t;
        atomicAdd(&g_pS[stripe], S);
        atomicAdd(&g_pQ[stripe], Q);
    }
}

// ---------------- GCN segment aggregation (batched gather pipeline) --------
template<bool ZATT>
__global__ void k_gcn_seg(const float* __restrict__ bias) {
    __shared__ float ss[8][128], sq[8][128];
    int w = threadIdx.x >> 5, l = threadIdx.x & 31;
    int d = blockIdx.x * 8 + w;            // NN = 50000 = 6250*8
    int deg = min(g_deg[d], BCAP);
    float dd = rsqrtf(1.0f + (float)deg);
    float4 b4 = ((const float4*)bias)[l];
    float4 self = load_row4(d, l);
    float dd2 = dd * dd;
    float4 acc = make_float4(fmaf(self.x, dd2, b4.x), fmaf(self.y, dd2, b4.y),
                             fmaf(self.z, dd2, b4.z), fmaf(self.w, dd2, b4.w));
    const int* bkt = &g_bkt[d * BCAP];
    int j = 0;
    for (; j + 8 <= deg; j += 8) {
        int sidx[8];
#pragma unroll
        for (int u = 0; u < 8; u++) sidx[u] = __ldg(&bkt[j + u]);
        float nrm[8]; float4 v[8];
#pragma unroll
        for (int u = 0; u < 8; u++) {
            nrm[u] = rsqrtf(1.0f + (float)g_deg[sidx[u]]) * dd;
            v[u] = load_row4(sidx[u], l);
        }
#pragma unroll
        for (int u = 0; u < 8; u++) acc4(acc, v[u], nrm[u]);
    }
    if (j + 4 <= deg) {
        int sidx[4];
#pragma unroll
        for (int u = 0; u < 4; u++) sidx[u] = __ldg(&bkt[j + u]);
        float nrm[4]; float4 v[4];
#pragma unroll
        for (int u = 0; u < 4; u++) {
            nrm[u] = rsqrtf(1.0f + (float)g_deg[sidx[u]]) * dd;
            v[u] = load_row4(sidx[u], l);
        }
#pragma unroll
        for (int u = 0; u < 4; u++) acc4(acc, v[u], nrm[u]);
        j += 4;
    }
    for (; j < deg; j++) {
        int s = __ldg(&bkt[j]);
        float nrm = rsqrtf(1.0f + (float)g_deg[s]) * dd;
        acc4(acc, load_row4(s, l), nrm);
    }
    ((float4*)&g_acc[d * HH])[l] = acc;
    if (ZATT && l == 0) { g_als[d] = 0.f; g_ald[d] = 0.f; }
    stats_stripe(acc, w, l, ss, sq);
}

// ---------------- GAT softmax + aggregation (single-pass, smem staged) -----
__global__ void k_gat_seg(const float* __restrict__ bias) {
    __shared__ float ss[8][128], sq[8][128];
    __shared__ float s_ex[8][BCAP];
    __shared__ int   s_idx[8][BCAP];
    int w = threadIdx.x >> 5, l = threadIdx.x & 31;
    int d = blockIdx.x * 8 + w;
    float ald_d = g_ald[d];
    float self_e = lrelu(g_als[d] + ald_d);
    int deg = min(g_deg[d], BCAP);
    const int* bkt = &g_bkt[d * BCAP];

    // lane-strided: each lane owns up to 2 neighbors
    int i0 = l, i1 = l + 32;
    int n0 = (i0 < deg) ? __ldg(&bkt[i0]) : 0;
    int n1 = (i1 < deg) ? __ldg(&bkt[i1]) : 0;
    float e0 = (i0 < deg) ? lrelu(g_als[n0] + ald_d) : -1e30f;
    float e1 = (i1 < deg) ? lrelu(g_als[n1] + ald_d) : -1e30f;
    float m = fmaxf(self_e, fmaxf(e0, e1));
#pragma unroll
    for (int o = 16; o; o >>= 1) m = fmaxf(m, __shfl_xor_sync(0xffffffffu, m, o));
    float ex0 = (i0 < deg) ? expf(e0 - m) : 0.f;
    float ex1 = (i1 < deg) ? expf(e1 - m) : 0.f;
    float den = ex0 + ex1;
#pragma unroll
    for (int o = 16; o; o >>= 1) den += __shfl_xor_sync(0xffffffffu, den, o);
    den += expf(self_e - m);
    float rden = 1.0f / den;
    if (i0 < deg) { s_ex[w][i0] = ex0; s_idx[w][i0] = n0; }
    if (i1 < deg) { s_ex[w][i1] = ex1; s_idx[w][i1] = n1; }
    __syncwarp();

    float4 b4 = ((const float4*)bias)[l];
    float a_self = expf(self_e - m) * rden;
    float4 self = load_row4(d, l);
    float4 acc = make_float4(fmaf(self.x, a_self, b4.x), fmaf(self.y, a_self, b4.y),
                             fmaf(self.z, a_self, b4.z), fmaf(self.w, a_self, b4.w));
    int j = 0;
    for (; j + 8 <= deg; j += 8) {
        int sidx[8]; float al[8];
#pragma unroll
        for (int u = 0; u < 8; u++) { sidx[u] = s_idx[w][j + u]; al[u] = s_ex[w][j + u] * rden; }
        float4 v[8];
#pragma unroll
        for (int u = 0; u < 8; u++) v[u] = load_row4(sidx[u], l);
#pragma unroll
        for (int u = 0; u < 8; u++) acc4(acc, v[u], al[u]);
    }
    if (j + 4 <= deg) {
        int sidx[4]; float al[4];
#pragma unroll
        for (int u = 0; u < 4; u++) { sidx[u] = s_idx[w][j + u]; al[u] = s_ex[w][j + u] * rden; }
        float4 v[4];
#pragma unroll
        for (int u = 0; u < 4; u++) v[u] = load_row4(sidx[u], l);
#pragma unroll
        for (int u = 0; u < 4; u++) acc4(acc, v[u], al[u]);
        j += 4;
    }
    for (; j < deg; j++) {
        float al = s_ex[w][j] * rden;
        acc4(acc, load_row4(s_idx[w][j], l), al);
    }
    ((float4*)&g_acc[d * HH])[l] = acc;
    stats_stripe(acc, w, l, ss, sq);
}

// ---------------- BN finalize (1 block, 512 thr; reads + re-zeros stripes) -
__global__ void k_bn_prep(const float* __restrict__ gamma, const float* __restrict__ beta) {
    __shared__ double sS[512], sQ[512];
    int t = threadIdx.x;
    int c = t & 127, grp = t >> 7;     // 4 stripe groups
    double S = 0.0, Q = 0.0;
    for (int s = grp; s < NSTRIPE; s += 4) {
        S += (double)g_pS[s * 128 + c];
        Q += (double)g_pQ[s * 128 + c];
        g_pS[s * 128 + c] = 0.f;
        g_pQ[s * 128 + c] = 0.f;
    }
    sS[t] = S; sQ[t] = Q;
    __syncthreads();
    if (grp == 0) {
        S = sS[c] + sS[c + 128] + sS[c + 256] + sS[c + 384];
        Q = sQ[c] + sQ[c + 128] + sQ[c + 256] + sQ[c + 384];
        double mu = S / (double)NN;
        double var = Q / (double)NN - mu * mu;
        float vf = (float)var; if (vf < 0.f) vf = 0.f;
        float sc = gamma[c] * rsqrtf(vf + EPSF);
        g_scale[c] = sc;
        g_shift[c] = beta[c] - (float)mu * sc;
    }
}

// ---------------- fused pool (BN3+ReLU) + 2-layer MLP, block per graph -----
__global__ void k_pool_mlp(const float* __restrict__ fw1, const float* __restrict__ fb1,
                           const float* __restrict__ fw2, const float* __restrict__ fb2,
                           float* __restrict__ out) {
    __shared__ float p[HH], z[HH], r[4];
    int g = blockIdx.x, t = threadIdx.x;     // 128 threads
    int s0 = g_gptr[g], s1 = g_gptr[g + 1];
    float sc = g_scale[t], sh = g_shift[t];
    float sum = 0.f;
    int i = s0;
    for (; i + 4 <= s1; i += 4) {
        float v0 = g_acc[(size_t)(i + 0) * HH + t];
        float v1 = g_acc[(size_t)(i + 1) * HH + t];
        float v2 = g_acc[(size_t)(i + 2) * HH + t];
        float v3 = g_acc[(size_t)(i + 3) * HH + t];
        sum += fmaxf(fmaf(v0, sc, sh), 0.f) + fmaxf(fmaf(v1, sc, sh), 0.f)
             + fmaxf(fmaf(v2, sc, sh), 0.f) + fmaxf(fmaf(v3, sc, sh), 0.f);
    }
    for (; i < s1; i++)
        sum += fmaxf(fmaf(g_acc[(size_t)i * HH + t], sc, sh), 0.f);
    float inv = 1.0f / fmaxf((float)(s1 - s0), 1.0f);
    p[t] = sum * inv;
    __syncthreads();
    float s = fb1[t];
#pragma unroll 8
    for (int k = 0; k < HH; k++) s = fmaf(p[k], fw1[k * HH + t], s);
    z[t] = fmaxf(s, 0.f);
    __syncthreads();
    float v = z[t] * fw2[t];
#pragma unroll
    for (int o = 16; o; o >>= 1) v += __shfl_xor_sync(0xffffffffu, v, o);
    if ((t & 31) == 0) r[t >> 5] = v;
    __syncthreads();
    if (t == 0) out[g] = r[0] + r[1] + r[2] + r[3] + fb2[0];
}

// ---------------- launch ----------------
extern "C" void kernel_launch(void* const* d_in, const int* in_sizes, int n_in,
                              void* d_out, int out_size) {
    const float* x       = (const float*)d_in[0];
    const int*   ei      = (const int*)d_in[1];
    const int*   batch   = (const int*)d_in[2];
    const float* W1      = (const float*)d_in[3];
    const float* b1      = (const float*)d_in[4];
    const float* g1      = (const float*)d_in[5];
    const float* be1     = (const float*)d_in[6];
    const float* Wg      = (const float*)d_in[7];
    const float* att_src = (const float*)d_in[8];
    const float* att_dst = (const float*)d_in[9];
    const float* bg      = (const float*)d_in[10];
    const float* g2      = (const float*)d_in[11];
    const float* be2     = (const float*)d_in[12];
    const float* W3      = (const float*)d_in[13];
    const float* b3      = (const float*)d_in[14];
    const float* g3      = (const float*)d_in[15];
    const float* be3     = (const float*)d_in[16];
    const float* fw1     = (const float*)d_in[17];
    const float* fb1     = (const float*)d_in[18];
    const float* fw2     = (const float*)d_in[19];
    const float* fb2     = (const float*)d_in[20];
    float* out = (float*)d_out;

    const int* src = ei;
    const int* dst = ei + EE;

    const int ZB   = (NSTRIPE * HH + 255) / 256;   // covers NN too? no: max(NN, 8192)
    const int NB   = (NN + 255) / 256;
    const int EB4  = (EE / 4 + 255) / 256;
    const int SEGB = NN / 8;                  // 6250 (exact)
    const int GEMB = (NN + 127) / 128;        // 391
    (void)ZB;

    // graph structure (+ graph boundary table from sorted batch)
    k_zero<<<NB, 256>>>(batch);
    k_fill<<<EB4, 256>>>(src, dst);

    // ---- layer 1: GCN ----
    k_gemm<false, false><<<GEMB, 256>>>(x, W1, nullptr, nullptr);
    k_gcn_seg<true><<<SEGB, 256>>>(b1);               // + zero att accumulators
    k_bn_prep<<<1, 512>>>(g1, be1);

    // ---- layer 2: GAT (BN1 fused into GEMM; att dots in epilogue) ----
    k_gemm<true, true><<<GEMB, 256>>>(nullptr, Wg, att_src, att_dst);
    k_gat_seg<<<SEGB, 256>>>(bg);
    k_bn_prep<<<1, 512>>>(g2, be2);

    // ---- layer 3: GCN (BN2 fused into GEMM) ----
    k_gemm<true, false><<<GEMB, 256>>>(nullptr, W3, nullptr, nullptr);
    k_gcn_seg<false><<<SEGB, 256>>>(b3);
    k_bn_prep<<<1, 512>>>(g3, be3);

    // ---- fused pool (BN3+ReLU) + MLP ----
    k_pool_mlp<<<GG, 128>>>(fw1, fb1, fw2, fb2, out);
}

// round 10
// speedup vs baseline: 1.4774x; 1.0632x over previous
#include <cuda_runtime.h>
#include <cuda_fp16.h>
#include <math.h>
#include <stdint.h>

// ---------------- problem constants ----------------
#define NN 50000
#define EE 600000
#define HH 128
#define GG 256
#define EPSF 1e-5f
#define SLOPE 0.2f
#define NSTRIPE 64
#define BCAP 64            // bucket capacity per node (Poisson(12) => P(>64) ~ 0)

// ---------------- scratch ----------------
__device__ __align__(16) __half2 g_tmp[NN * (HH / 2)];  // GEMM output, fp16 payload
__device__ __align__(16) float g_acc[NN * HH];          // aggregated pre-BN activations
__device__ float g_dis[NN];
__device__ float g_als[NN], g_ald[NN];
__device__ int   g_deg[NN];
__device__ int   g_bkt[NN * BCAP];               // direct-bucket CSR
__device__ int   g_gptr[GG + 1];                 // graph row ranges (batch is sorted)
__device__ float g_pS[NSTRIPE * HH], g_pQ[NSTRIPE * HH];
__device__ __align__(16) float g_scale[HH], g_shift[HH];

__device__ __forceinline__ float lrelu(float x) { return x > 0.f ? x : SLOPE * x; }

__device__ __forceinline__ float to_tf32(float x) {
    float r;
    asm("cvt.rna.tf32.f32 %0, %1;" : "=f"(r) : "f"(x));
    return r;
}

// gather 4 floats (cols 4l..4l+3) of node s from fp16 payload
__device__ __forceinline__ float4 load_row4(int s, int l) {
    uint2 u = *(const uint2*)&g_tmp[s * (HH / 2) + l * 2];
    float2 f0 = __half22float2(*(__half2*)&u.x);
    float2 f1 = __half22float2(*(__half2*)&u.y);
    return make_float4(f0.x, f0.y, f1.x, f1.y);
}

__device__ __forceinline__ void acc4(float4& a, float4 v, float wt) {
    a.x = fmaf(v.x, wt, a.x); a.y = fmaf(v.y, wt, a.y);
    a.z = fmaf(v.z, wt, a.z); a.w = fmaf(v.w, wt, a.w);
}
__device__ __forceinline__ void add4(float4& a, float4 v) {
    a.x += v.x; a.y += v.y; a.z += v.z; a.w += v.w;
}

// ---------------- zero + graph boundaries (batch is sorted) ----------------
__global__ void k_zero(const int* __restrict__ batch) {
    int i = blockIdx.x * blockDim.x + threadIdx.x;
    if (i < NN) {
        g_deg[i] = 0;
        int b = batch[i];
        if (i == 0) {
            for (int g = 0; g <= b; g++) g_gptr[g] = 0;
        } else {
            int pb = batch[i - 1];
            for (int g = pb + 1; g <= b; g++) g_gptr[g] = i;
        }
        if (i == NN - 1) {
            for (int g = b + 1; g <= GG; g++) g_gptr[g] = NN;
        }
    }
    if (i < NSTRIPE * HH) { g_pS[i] = 0.f; g_pQ[i] = 0.f; }
}
__global__ void k_fill(const int* __restrict__ src, const int* __restrict__ dst) {
    int e0 = (blockIdx.x * blockDim.x + threadIdx.x) * 4;
    if (e0 >= EE) return;
    int4 s4 = *(const int4*)&src[e0];
    int4 d4 = *(const int4*)&dst[e0];
    int p0 = atomicAdd(&g_deg[d4.x], 1);
    int p1 = atomicAdd(&g_deg[d4.y], 1);
    int p2 = atomicAdd(&g_deg[d4.z], 1);
    int p3 = atomicAdd(&g_deg[d4.w], 1);
    if (p0 < BCAP) g_bkt[d4.x * BCAP + p0] = s4.x;
    if (p1 < BCAP) g_bkt[d4.y * BCAP + p1] = s4.y;
    if (p2 < BCAP) g_bkt[d4.z * BCAP + p2] = s4.z;
    if (p3 < BCAP) g_bkt[d4.w * BCAP + p3] = s4.w;
}
__global__ void k_dis() {
    int i = blockIdx.x * blockDim.x + threadIdx.x;
    if (i < NN) g_dis[i] = rsqrtf(1.0f + (float)g_deg[i]);
}

// ---------------- TF32 tensor-core GEMM, cp.async 2-stage pipeline ----------
// SCALE: multiply output row r by g_dis[r] before fp16 store (GCN pre-scaling).
template<bool BN, bool ATT, bool SCALE>
__global__ __launch_bounds__(256, 2)
void k_gemm(const float* __restrict__ Aext, const float* __restrict__ W,
            const float* __restrict__ av_s, const float* __restrict__ av_d) {
    __shared__ float As[2][128][20];     // [stage][row][k] raw fp32, k-chunk=16
    __shared__ float Bs[2][16][136];     // [stage][k][n]   raw fp32
    __shared__ float s_sc[128], s_sh[128], s_as[128], s_ad[128];
    const float* A = BN ? (const float*)g_acc : Aext;
    int t = threadIdx.x;
    if (t < 128) {
        if (BN)  { s_sc[t] = g_scale[t]; s_sh[t] = g_shift[t]; }
        if (ATT) { s_as[t] = av_s[t];    s_ad[t] = av_d[t]; }
    }
    int row0 = blockIdx.x * 128;
    int warpId = t >> 5, lane = t & 31;
    int wm = warpId >> 1, wn = warpId & 1;   // 4 x 2 warp grid
    int gp = lane >> 2, qi = lane & 3;

    int arow = t >> 2;            // 0..63 (two passes of 64 rows)
    int ac4  = (t & 3) * 4;       // 0,4,8,12
    int brow = t >> 5;            // 0..7  (two passes of 8 rows)
    int bc4  = (t & 31) * 4;

    float acc[2][8][4];
#pragma unroll
    for (int mt = 0; mt < 2; mt++)
#pragma unroll
        for (int nt = 0; nt < 8; nt++)
#pragma unroll
            for (int j = 0; j < 4; j++) acc[mt][nt][j] = 0.f;

    auto stage = [&](int st, int kt) {
#pragma unroll
        for (int p = 0; p < 2; p++) {
            int r = p * 64 + arow;
            int grow = row0 + r;
            uint32_t sa = (uint32_t)__cvta_generic_to_shared(&As[st][r][ac4]);
            const float* gp_ = &A[(size_t)grow * 128 + kt + ac4];
            int sz = (grow < NN) ? 16 : 0;
            asm volatile("cp.async.cg.shared.global [%0], [%1], 16, %2;"
                         :: "r"(sa), "l"(gp_), "r"(sz));
        }
#pragma unroll
        for (int p = 0; p < 2; p++) {
            int r = p * 8 + brow;
            uint32_t sa = (uint32_t)__cvta_generic_to_shared(&Bs[st][r][bc4]);
            const float* gp_ = &W[(kt + r) * 128 + bc4];
            asm volatile("cp.async.cg.shared.global [%0], [%1], 16, 16;"
                         :: "r"(sa), "l"(gp_));
        }
        asm volatile("cp.async.commit_group;");
    };

    auto compute = [&](int st, int kt) {
#pragma unroll
        for (int k8 = 0; k8 < 16; k8 += 8) {
            float sc0 = 0.f, sh0 = 0.f, sc4 = 0.f, sh4 = 0.f;
            if (BN) {
                sc0 = s_sc[kt + k8 + qi];     sh0 = s_sh[kt + k8 + qi];
                sc4 = s_sc[kt + k8 + qi + 4]; sh4 = s_sh[kt + k8 + qi + 4];
            }
            uint32_t a[2][4], b[8][2];
#pragma unroll
            for (int mt = 0; mt < 2; mt++) {
                int rb = wm * 32 + mt * 16 + gp;
                float a0 = As[st][rb][k8 + qi],     a1 = As[st][rb + 8][k8 + qi];
                float a2 = As[st][rb][k8 + qi + 4], a3 = As[st][rb + 8][k8 + qi + 4];
                if (BN) {
                    a0 = fmaxf(fmaf(a0, sc0, sh0), 0.f);
                    a1 = fmaxf(fmaf(a1, sc0, sh0), 0.f);
                    a2 = fmaxf(fmaf(a2, sc4, sh4), 0.f);
                    a3 = fmaxf(fmaf(a3, sc4, sh4), 0.f);
                }
                a[mt][0] = __float_as_uint(to_tf32(a0));
                a[mt][1] = __float_as_uint(to_tf32(a1));
                a[mt][2] = __float_as_uint(to_tf32(a2));
                a[mt][3] = __float_as_uint(to_tf32(a3));
            }
#pragma unroll
            for (int nt = 0; nt < 8; nt++) {
                int cb = wn * 64 + nt * 8 + gp;
                b[nt][0] = __float_as_uint(to_tf32(Bs[st][k8 + qi][cb]));
                b[nt][1] = __float_as_uint(to_tf32(Bs[st][k8 + qi + 4][cb]));
            }
#pragma unroll
            for (int mt = 0; mt < 2; mt++)
#pragma unroll
                for (int nt = 0; nt < 8; nt++) {
                    asm volatile(
                        "mma.sync.aligned.m16n8k8.row.col.f32.tf32.tf32.f32 "
                        "{%0,%1,%2,%3},{%4,%5,%6,%7},{%8,%9},{%0,%1,%2,%3};"
                        : "+f"(acc[mt][nt][0]), "+f"(acc[mt][nt][1]),
                          "+f"(acc[mt][nt][2]), "+f"(acc[mt][nt][3])
                        : "r"(a[mt][0]), "r"(a[mt][1]), "r"(a[mt][2]), "r"(a[mt][3]),
                          "r"(b[nt][0]), "r"(b[nt][1]));
                }
        }
    };

    stage(0, 0);
    stage(1, 16);
#pragma unroll
    for (int i = 0; i < 8; i++) {
        if (i < 7) asm volatile("cp.async.wait_group 1;");
        else       asm volatile("cp.async.wait_group 0;");
        __syncthreads();
        compute(i & 1, i * 16);
        __syncthreads();
        if (i + 2 < 8) stage(i & 1, (i + 2) * 16);
    }

    // epilogue: fp16 store (optionally row-scaled) + optional att dots
#pragma unroll
    for (int mt = 0; mt < 2; mt++) {
#pragma unroll
        for (int h = 0; h < 2; h++) {
            int row = row0 + wm * 32 + mt * 16 + h * 8 + gp;
            bool ok = (row < NN);
            float drow = (SCALE && ok) ? g_dis[row] : 1.0f;
            float ps = 0.f, pd = 0.f;
#pragma unroll
            for (int nt = 0; nt < 8; nt++) {
                int col = wn * 64 + nt * 8 + 2 * qi;
                float c0 = acc[mt][nt][2 * h], c1 = acc[mt][nt][2 * h + 1];
                if (ok) {
                    float o0 = SCALE ? c0 * drow : c0;
                    float o1 = SCALE ? c1 * drow : c1;
                    g_tmp[row * (HH / 2) + (col >> 1)] = __floats2half2_rn(o0, o1);
                }
                if (ATT) {
                    ps = fmaf(c0, s_as[col], fmaf(c1, s_as[col + 1], ps));
                    pd = fmaf(c0, s_ad[col], fmaf(c1, s_ad[col + 1], pd));
                }
            }
            if (ATT) {
                ps += __shfl_xor_sync(0xffffffffu, ps, 1);
                ps += __shfl_xor_sync(0xffffffffu, ps, 2);
                pd += __shfl_xor_sync(0xffffffffu, pd, 1);
                pd += __shfl_xor_sync(0xffffffffu, pd, 2);
                if (qi == 0 && ok) {
                    atomicAdd(&g_als[row], ps);
                    atomicAdd(&g_ald[row], pd);
                }
            }
        }
    }
}

// ---------------- shared stats accumulation ----------------
__device__ __forceinline__ void stats_stripe(
    float4 a, int w, int l, float (*ss)[128], float (*sq)[128]) {
    *(float4*)&ss[w][l * 4] = a;
    *(float4*)&sq[w][l * 4] = make_float4(a.x * a.x, a.y * a.y, a.z * a.z, a.w * a.w);
    __syncthreads();
    int t = threadIdx.x;
    if (t < 128) {
        float S = 0.f, Q = 0.f;
#pragma unroll
        for (int ww = 0; ww < 8; ww++) { S += ss[ww][t]; Q += sq[ww][t]; }
        int stripe = (blockIdx.x & (NSTRIPE - 1)) * 128 + t;
        atomicAdd(&g_pS[stripe], S);
        atomicAdd(&g_pQ[stripe], Q);
    }
}

// ---------------- GCN segment aggregation (pure sum; payload pre-scaled) ---
template<bool ZATT>
__global__ void k_gcn_seg(const float* __restrict__ bias) {
    __shared__ float ss[8][128], sq[8][128];
    int w = threadIdx.x >> 5, l = threadIdx.x & 31;
    int d = blockIdx.x * 8 + w;            // NN = 50000 = 6250*8
    int deg = min(g_deg[d], BCAP);
    float dd = g_dis[d];
    // rows in g_tmp are h[s]*dis[s]; self row = h[d]*dis[d]
    float4 sum = load_row4(d, l);
    const int* bkt = &g_bkt[d * BCAP];
    int j = 0;
    for (; j + 8 <= deg; j += 8) {
        int sidx[8];
#pragma unroll
        for (int u = 0; u < 8; u++) sidx[u] = __ldg(&bkt[j + u]);
        float4 v[8];
#pragma unroll
        for (int u = 0; u < 8; u++) v[u] = load_row4(sidx[u], l);
#pragma unroll
        for (int u = 0; u < 8; u++) add4(sum, v[u]);
    }
    if (j + 4 <= deg) {
        int sidx[4];
#pragma unroll
        for (int u = 0; u < 4; u++) sidx[u] = __ldg(&bkt[j + u]);
        float4 v[4];
#pragma unroll
        for (int u = 0; u < 4; u++) v[u] = load_row4(sidx[u], l);
#pragma unroll
        for (int u = 0; u < 4; u++) add4(sum, v[u]);
        j += 4;
    }
    for (; j < deg; j++) {
        int s = __ldg(&bkt[j]);
        add4(sum, load_row4(s, l));
    }
    float4 b4 = ((const float4*)bias)[l];
    float4 acc = make_float4(fmaf(sum.x, dd, b4.x), fmaf(sum.y, dd, b4.y),
                             fmaf(sum.z, dd, b4.z), fmaf(sum.w, dd, b4.w));
    ((float4*)&g_acc[d * HH])[l] = acc;
    if (ZATT && l == 0) { g_als[d] = 0.f; g_ald[d] = 0.f; }
    stats_stripe(acc, w, l, ss, sq);
}

// ---------------- GAT softmax + aggregation (single-pass, smem staged) -----
__global__ void k_gat_seg(const float* __restrict__ bias) {
    __shared__ float ss[8][128], sq[8][128];
    __shared__ float s_ex[8][BCAP];
    __shared__ int   s_idx[8][BCAP];
    int w = threadIdx.x >> 5, l = threadIdx.x & 31;
    int d = blockIdx.x * 8 + w;
    float ald_d = g_ald[d];
    float self_e = lrelu(g_als[d] + ald_d);
    int deg = min(g_deg[d], BCAP);
    const int* bkt = &g_bkt[d * BCAP];

    // lane-strided: each lane owns up to 2 neighbors
    int i0 = l, i1 = l + 32;
    int n0 = (i0 < deg) ? __ldg(&bkt[i0]) : 0;
    int n1 = (i1 < deg) ? __ldg(&bkt[i1]) : 0;
    float e0 = (i0 < deg) ? lrelu(g_als[n0] + ald_d) : -1e30f;
    float e1 = (i1 < deg) ? lrelu(g_als[n1] + ald_d) : -1e30f;
    float m = fmaxf(self_e, fmaxf(e0, e1));
#pragma unroll
    for (int o = 16; o; o >>= 1) m = fmaxf(m, __shfl_xor_sync(0xffffffffu, m, o));
    float ex0 = (i0 < deg) ? expf(e0 - m) : 0.f;
    float ex1 = (i1 < deg) ? expf(e1 - m) : 0.f;
    float den = ex0 + ex1;
#pragma unroll
    for (int o = 16; o; o >>= 1) den += __shfl_xor_sync(0xffffffffu, den, o);
    den += expf(self_e - m);
    float rden = 1.0f / den;
    if (i0 < deg) { s_ex[w][i0] = ex0; s_idx[w][i0] = n0; }
    if (i1 < deg) { s_ex[w][i1] = ex1; s_idx[w][i1] = n1; }
    __syncwarp();

    float4 b4 = ((const float4*)bias)[l];
    float a_self = expf(self_e - m) * rden;
    float4 self = load_row4(d, l);
    float4 acc = make_float4(fmaf(self.x, a_self, b4.x), fmaf(self.y, a_self, b4.y),
                             fmaf(self.z, a_self, b4.z), fmaf(self.w, a_self, b4.w));
    int j = 0;
    for (; j + 8 <= deg; j += 8) {
        int sidx[8]; float al[8];
#pragma unroll
        for (int u = 0; u < 8; u++) { sidx[u] = s_idx[w][j + u]; al[u] = s_ex[w][j + u] * rden; }
        float4 v[8];
#pragma unroll
        for (int u = 0; u < 8; u++) v[u] = load_row4(sidx[u], l);
#pragma unroll
        for (int u = 0; u < 8; u++) acc4(acc, v[u], al[u]);
    }
    if (j + 4 <= deg) {
        int sidx[4]; float al[4];
#pragma unroll
        for (int u = 0; u < 4; u++) { sidx[u] = s_idx[w][j + u]; al[u] = s_ex[w][j + u] * rden; }
        float4 v[4];
#pragma unroll
        for (int u = 0; u < 4; u++) v[u] = load_row4(sidx[u], l);
#pragma unroll
        for (int u = 0; u < 4; u++) acc4(acc, v[u], al[u]);
        j += 4;
    }
    for (; j < deg; j++) {
        float al = s_ex[w][j] * rden;
        acc4(acc, load_row4(s_idx[w][j], l), al);
    }
    ((float4*)&g_acc[d * HH])[l] = acc;
    stats_stripe(acc, w, l, ss, sq);
}

// ---------------- BN finalize (1 block, 512 thr; reads + re-zeros stripes) -
__global__ void k_bn_prep(const float* __restrict__ gamma, const float* __restrict__ beta) {
    __shared__ double sS[512], sQ[512];
    int t = threadIdx.x;
    int c = t & 127, grp = t >> 7;     // 4 stripe groups
    double S = 0.0, Q = 0.0;
    for (int s = grp; s < NSTRIPE; s += 4) {
        S += (double)g_pS[s * 128 + c];
        Q += (double)g_pQ[s * 128 + c];
        g_pS[s * 128 + c] = 0.f;
        g_pQ[s * 128 + c] = 0.f;
    }
    sS[t] = S; sQ[t] = Q;
    __syncthreads();
    if (grp == 0) {
        S = sS[c] + sS[c + 128] + sS[c + 256] + sS[c + 384];
        Q = sQ[c] + sQ[c + 128] + sQ[c + 256] + sQ[c + 384];
        double mu = S / (double)NN;
        double var = Q / (double)NN - mu * mu;
        float vf = (float)var; if (vf < 0.f) vf = 0.f;
        float sc = gamma[c] * rsqrtf(vf + EPSF);
        g_scale[c] = sc;
        g_shift[c] = beta[c] - (float)mu * sc;
    }
}

// ---------------- fused pool (BN3+ReLU) + 2-layer MLP, block per graph -----
__global__ void k_pool_mlp(const float* __restrict__ fw1, const float* __restrict__ fb1,
                           const float* __restrict__ fw2, const float* __restrict__ fb2,
                           float* __restrict__ out) {
    __shared__ float p[HH], z[HH], r[4];
    int g = blockIdx.x, t = threadIdx.x;     // 128 threads
    int s0 = g_gptr[g], s1 = g_gptr[g + 1];
    float sc = g_scale[t], sh = g_shift[t];
    float sum = 0.f;
    int i = s0;
    for (; i + 4 <= s1; i += 4) {
        float v0 = g_acc[(size_t)(i + 0) * HH + t];
        float v1 = g_acc[(size_t)(i + 1) * HH + t];
        float v2 = g_acc[(size_t)(i + 2) * HH + t];
        float v3 = g_acc[(size_t)(i + 3) * HH + t];
        sum += fmaxf(fmaf(v0, sc, sh), 0.f) + fmaxf(fmaf(v1, sc, sh), 0.f)
             + fmaxf(fmaf(v2, sc, sh), 0.f) + fmaxf(fmaf(v3, sc, sh), 0.f);
    }
    for (; i < s1; i++)
        sum += fmaxf(fmaf(g_acc[(size_t)i * HH + t], sc, sh), 0.f);
    float inv = 1.0f / fmaxf((float)(s1 - s0), 1.0f);
    p[t] = sum * inv;
    __syncthreads();
    float s = fb1[t];
#pragma unroll 8
    for (int k = 0; k < HH; k++) s = fmaf(p[k], fw1[k * HH + t], s);
    z[t] = fmaxf(s, 0.f);
    __syncthreads();
    float v = z[t] * fw2[t];
#pragma unroll
    for (int o = 16; o; o >>= 1) v += __shfl_xor_sync(0xffffffffu, v, o);
    if ((t & 31) == 0) r[t >> 5] = v;
    __syncthreads();
    if (t == 0) out[g] = r[0] + r[1] + r[2] + r[3] + fb2[0];
}

// ---------------- launch ----------------
extern "C" void kernel_launch(void* const* d_in, const int* in_sizes, int n_in,
                              void* d_out, int out_size) {
    const float* x       = (const float*)d_in[0];
    const int*   ei      = (const int*)d_in[1];
    const int*   batch   = (const int*)d_in[2];
    const float* W1      = (const float*)d_in[3];
    const float* b1      = (const float*)d_in[4];
    const float* g1      = (const float*)d_in[5];
    const float* be1     = (const float*)d_in[6];
    const float* Wg      = (const float*)d_in[7];
    const float* att_src = (const float*)d_in[8];
    const float* att_dst = (const float*)d_in[9];
    const float* bg      = (const float*)d_in[10];
    const float* g2      = (const float*)d_in[11];
    const float* be2     = (const float*)d_in[12];
    const float* W3      = (const float*)d_in[13];
    const float* b3      = (const float*)d_in[14];
    const float* g3      = (const float*)d_in[15];
    const float* be3     = (const float*)d_in[16];
    const float* fw1     = (const float*)d_in[17];
    const float* fb1     = (const float*)d_in[18];
    const float* fw2     = (const float*)d_in[19];
    const float* fb2     = (const float*)d_in[20];
    float* out = (float*)d_out;

    const int* src = ei;
    const int* dst = ei + EE;

    const int NB   = (NN + 255) / 256;
    const int EB4  = (EE / 4 + 255) / 256;
    const int SEGB = NN / 8;                  // 6250 (exact)
    const int GEMB = (NN + 127) / 128;        // 391

    // graph structure (+ graph boundary table from sorted batch)
    k_zero<<<NB, 256>>>(batch);
    k_fill<<<EB4, 256>>>(src, dst);
    k_dis<<<NB, 256>>>();

    // ---- layer 1: GCN (payload pre-scaled by dis in GEMM epilogue) ----
    k_gemm<false, false, true><<<GEMB, 256>>>(x, W1, nullptr, nullptr);
    k_gcn_seg<true><<<SEGB, 256>>>(b1);               // + zero att accumulators
    k_bn_prep<<<1, 512>>>(g1, be1);

    // ---- layer 2: GAT (BN1 fused into GEMM; att dots in epilogue) ----
    k_gemm<true, true, false><<<GEMB, 256>>>(nullptr, Wg, att_src, att_dst);
    k_gat_seg<<<SEGB, 256>>>(bg);
    k_bn_prep<<<1, 512>>>(g2, be2);

    // ---- layer 3: GCN (BN2 fused into GEMM; payload pre-scaled) ----
    k_gemm<true, false, true><<<GEMB, 256>>>(nullptr, W3, nullptr, nullptr);
    k_gcn_seg<false><<<SEGB, 256>>>(b3);
    k_bn_prep<<<1, 512>>>(g3, be3);

    // ---- fused pool (BN3+ReLU) + MLP ----
    k_pool_mlp<<<GG, 128>>>(fw1, fb1, fw2, fb2, out);
}